// round 1
// baseline (speedup 1.0000x reference)
#include <cuda_runtime.h>
#include <math.h>

#define D      256
#define NTOK   32768
#define ND     (NTOK * D)          // 8388608
#define DD     (D * D)             // 65536
#define LRc    1e-3f
#define WDc    1e-2f
#define EPSc   1e-8f
#define KSPLIT 128
#define KROWS  (NTOK / KSPLIT)     // 256

// ---------------- scratch (device globals: allocation-free) ----------------
__device__ float g_keys[ND];
__device__ float g_queries[ND];
__device__ float g_values[ND];
__device__ float g_h1[ND];
__device__ float g_z1[ND];
__device__ float g_z2[ND];
__device__ float g_h2[ND];
__device__ float g_dp[ND];
__device__ float g_dz2[ND];
__device__ float g_dz1[ND];
__device__ float g_alr[NTOK];
__device__ float g_gw_part[KSPLIT * DD];
__device__ float g_gb_part[256 * D];
__device__ float g_gW[2 * DD];
__device__ float g_gb[2 * D];
__device__ float g_nW[2 * DD];
__device__ float g_nb[2 * D];

__device__ __forceinline__ float sigmoidf_(float z) { return 1.0f / (1.0f + expf(-z)); }

// ---------------- main GEMM: C[M=NTOK,256] = A[M,256] @ B(256,256) ----------
// MODE 0: O1 = A@B
// MODE 1: z = A@B + bias; O1 = z; O2 = A + silu(z)        (forward layer)
// MODE 2: dh = E1 + A@B^T; O1 = dh * silu'(E2)            (backward dz)
template <int MODE, bool TB>
__launch_bounds__(256)
__global__ void gemm_k(const float* __restrict__ A, const float* __restrict__ B,
                       const float* __restrict__ bias,
                       const float* __restrict__ E1, const float* __restrict__ E2,
                       float* __restrict__ O1, float* __restrict__ O2)
{
    __shared__ float As[16][68];   // [k][m], padded, 16B-aligned rows (68 = 4*17)
    __shared__ float Bs[16][64];   // [k][n]

    const int tid = threadIdx.x;
    const int tx = tid & 15;       // n micro
    const int ty = tid >> 4;       // m micro
    const int m0 = blockIdx.y * 64;
    const int n0 = blockIdx.x * 64;

    float acc[4][4] = {};

    const int arow = tid >> 2;            // 0..63
    const int ac4  = (tid & 3) * 4;       // 0,4,8,12

    for (int t = 0; t < 16; ++t) {
        const int k0 = t * 16;
        // A tile 64x16 -> As[k][m]
        float4 a4 = *(const float4*)(A + (m0 + arow) * D + k0 + ac4);
        As[ac4 + 0][arow] = a4.x;
        As[ac4 + 1][arow] = a4.y;
        As[ac4 + 2][arow] = a4.z;
        As[ac4 + 3][arow] = a4.w;
        // B tile 16x64 -> Bs[k][n]
        if (!TB) {
            const int bk = tid >> 4;          // 0..15
            const int bn = (tid & 15) * 4;    // 0..60
            float4 b4 = *(const float4*)(B + (k0 + bk) * D + n0 + bn);
            *(float4*)&Bs[bk][bn] = b4;
        } else {
            const int bn = tid >> 2;          // 0..63
            const int bk = (tid & 3) * 4;     // 0,4,8,12
            float4 b4 = *(const float4*)(B + (n0 + bn) * D + k0 + bk);
            Bs[bk + 0][bn] = b4.x;
            Bs[bk + 1][bn] = b4.y;
            Bs[bk + 2][bn] = b4.z;
            Bs[bk + 3][bn] = b4.w;
        }
        __syncthreads();
        #pragma unroll
        for (int kk = 0; kk < 16; ++kk) {
            float4 av = *(const float4*)&As[kk][ty * 4];
            float4 bv = *(const float4*)&Bs[kk][tx * 4];
            float ar[4] = {av.x, av.y, av.z, av.w};
            float br[4] = {bv.x, bv.y, bv.z, bv.w};
            #pragma unroll
            for (int i = 0; i < 4; ++i)
                #pragma unroll
                for (int j = 0; j < 4; ++j)
                    acc[i][j] = fmaf(ar[i], br[j], acc[i][j]);
        }
        __syncthreads();
    }

    #pragma unroll
    for (int i = 0; i < 4; ++i) {
        const int row = m0 + ty * 4 + i;
        const int col = n0 + tx * 4;
        const int idx = row * D + col;
        if (MODE == 0) {
            float4 o = {acc[i][0], acc[i][1], acc[i][2], acc[i][3]};
            *(float4*)(O1 + idx) = o;
        } else if (MODE == 1) {
            float4 bb  = *(const float4*)(bias + col);
            float4 ain = *(const float4*)(A + idx);
            float zz[4] = {acc[i][0] + bb.x, acc[i][1] + bb.y,
                           acc[i][2] + bb.z, acc[i][3] + bb.w};
            float aa[4] = {ain.x, ain.y, ain.z, ain.w};
            float hh[4];
            #pragma unroll
            for (int j = 0; j < 4; ++j) {
                float s = sigmoidf_(zz[j]);
                hh[j] = aa[j] + zz[j] * s;
            }
            float4 oz = {zz[0], zz[1], zz[2], zz[3]};
            float4 oh = {hh[0], hh[1], hh[2], hh[3]};
            *(float4*)(O1 + idx) = oz;
            *(float4*)(O2 + idx) = oh;
        } else {
            float4 e1 = *(const float4*)(E1 + idx);
            float4 e2 = *(const float4*)(E2 + idx);
            float dh[4] = {e1.x + acc[i][0], e1.y + acc[i][1],
                           e1.z + acc[i][2], e1.w + acc[i][3]};
            float zz[4] = {e2.x, e2.y, e2.z, e2.w};
            float oo[4];
            #pragma unroll
            for (int j = 0; j < 4; ++j) {
                float s = sigmoidf_(zz[j]);
                oo[j] = dh[j] * s * (1.0f + zz[j] * (1.0f - s));
            }
            float4 o = {oo[0], oo[1], oo[2], oo[3]};
            *(float4*)(O1 + idx) = o;
        }
    }
}

// ------------- weight-grad GEMM: part[z][k1,k2] += A[n,k1]*Bm[n,k2] ---------
// grid (4,4,KSPLIT); each block: 64x64 output tile over KROWS rows of n.
__launch_bounds__(256)
__global__ void gw_gemm_k(const float* __restrict__ A, const float* __restrict__ Bm,
                          float* __restrict__ part)
{
    __shared__ float As[16][64];   // [n][k1]
    __shared__ float Bs[16][64];   // [n][k2]
    const int tid = threadIdx.x;
    const int tx = tid & 15;
    const int ty = tid >> 4;
    const int m0 = blockIdx.y * 64;
    const int n0 = blockIdx.x * 64;
    const int nbase = blockIdx.z * KROWS;

    float acc[4][4] = {};
    const int lm = (tid & 15) * 4;  // 0..60
    const int ln = tid >> 4;        // 0..15

    for (int t = 0; t < KROWS / 16; ++t) {
        const int r0 = nbase + t * 16;
        float4 a4 = *(const float4*)(A  + (r0 + ln) * D + m0 + lm);
        float4 b4 = *(const float4*)(Bm + (r0 + ln) * D + n0 + lm);
        *(float4*)&As[ln][lm] = a4;
        *(float4*)&Bs[ln][lm] = b4;
        __syncthreads();
        #pragma unroll
        for (int kk = 0; kk < 16; ++kk) {
            float4 av = *(const float4*)&As[kk][ty * 4];
            float4 bv = *(const float4*)&Bs[kk][tx * 4];
            float ar[4] = {av.x, av.y, av.z, av.w};
            float br[4] = {bv.x, bv.y, bv.z, bv.w};
            #pragma unroll
            for (int i = 0; i < 4; ++i)
                #pragma unroll
                for (int j = 0; j < 4; ++j)
                    acc[i][j] = fmaf(ar[i], br[j], acc[i][j]);
        }
        __syncthreads();
    }
    #pragma unroll
    for (int i = 0; i < 4; ++i) {
        const int row = m0 + ty * 4 + i;
        const int col = n0 + tx * 4;
        float4 o = {acc[i][0], acc[i][1], acc[i][2], acc[i][3]};
        *(float4*)(part + (size_t)blockIdx.z * DD + row * D + col) = o;
    }
}

__global__ void gw_red_k(const float* __restrict__ part, float* __restrict__ gW)
{
    const int i = blockIdx.x * 256 + threadIdx.x;   // 0..DD-1
    float s = 0.0f;
    for (int ks = 0; ks < KSPLIT; ++ks) s += part[(size_t)ks * DD + i];
    gW[i] = s;
}

// ------------- adaptive lr: one warp per token ------------------------------
__global__ void alr_k(const float* __restrict__ x, const float* __restrict__ Wlr,
                      const float* __restrict__ blr, float* __restrict__ alr)
{
    const int warp = threadIdx.x >> 5;
    const int lane = threadIdx.x & 31;
    const int tok = blockIdx.x * 8 + warp;
    float s = 0.0f;
    #pragma unroll
    for (int k = lane; k < D; k += 32) s += x[tok * D + k] * Wlr[k];
    #pragma unroll
    for (int o = 16; o > 0; o >>= 1) s += __shfl_xor_sync(0xffffffffu, s, o);
    if (lane == 0) alr[tok] = 0.1f * sigmoidf_(s + blr[0]);
}

// ------------- dp / dz2 -----------------------------------------------------
__global__ void dp_k(const float* __restrict__ h2, const float* __restrict__ v,
                     const float* __restrict__ z2, const float* __restrict__ alr,
                     float* __restrict__ dp, float* __restrict__ dz2)
{
    const int idx = blockIdx.x * 256 + threadIdx.x;
    const int n = idx >> 8;
    const float c = (2.0f / (float)D) * alr[n];
    const float d = c * (h2[idx] - v[idx]);
    const float z = z2[idx];
    const float s = sigmoidf_(z);
    dp[idx]  = d;
    dz2[idx] = d * s * (1.0f + z * (1.0f - s));
}

// ------------- column sums (bias grads), deterministic two-stage ------------
__global__ void colsum_part_k(const float* __restrict__ Z, float* __restrict__ part)
{
    const int b = blockIdx.x;       // 256 blocks x 128 rows
    const int j = threadIdx.x;
    float s = 0.0f;
    const int base = b * 128;
    for (int r = 0; r < 128; ++r) s += Z[(base + r) * D + j];
    part[b * D + j] = s;
}

__global__ void colsum_red_k(const float* __restrict__ part, float* __restrict__ gb)
{
    const int j = threadIdx.x;
    float s = 0.0f;
    for (int b = 0; b < 256; ++b) s += part[b * D + j];
    gb[j] = s;
}

// ------------- AdamW step (m_hat=g, v_hat=g^2) + write -grads to out --------
__global__ void adamw_k(const float* __restrict__ Ws, const float* __restrict__ bs,
                        const float* __restrict__ gW, const float* __restrict__ gb,
                        float* __restrict__ nW, float* __restrict__ nb,
                        float* __restrict__ out)
{
    const int idx = blockIdx.x * 256 + threadIdx.x;
    const float decay = 1.0f - LRc * WDc;
    if (idx < 2 * DD) {
        const float g = gW[idx];
        nW[idx] = Ws[idx] * decay - LRc * g / (fabsf(g) + EPSc);
        out[ND + idx] = -g;
    } else if (idx < 2 * DD + 2 * D) {
        const int b = idx - 2 * DD;
        const float g = gb[b];
        nb[b] = bs[b] * decay - LRc * g / (fabsf(g) + EPSc);
        out[ND + 2 * DD + b] = -g;
    }
}

// ---------------------------------------------------------------------------
extern "C" void kernel_launch(void* const* d_in, const int* in_sizes, int n_in,
                              void* d_out, int out_size)
{
    const float* x   = (const float*)d_in[0];
    const float* Wk  = (const float*)d_in[1];
    const float* Wq  = (const float*)d_in[2];
    const float* Wv  = (const float*)d_in[3];
    const float* Wlr = (const float*)d_in[4];
    const float* blr = (const float*)d_in[5];
    const float* Ws  = (const float*)d_in[6];
    const float* bs  = (const float*)d_in[7];
    float* out = (float*)d_out;

    float *keys, *queries, *values, *h1, *z1, *z2, *h2, *dp, *dz2, *dz1, *alr;
    float *gw_part, *gb_part, *gW, *gb, *nW, *nb;
    cudaGetSymbolAddress((void**)&keys,    g_keys);
    cudaGetSymbolAddress((void**)&queries, g_queries);
    cudaGetSymbolAddress((void**)&values,  g_values);
    cudaGetSymbolAddress((void**)&h1,      g_h1);
    cudaGetSymbolAddress((void**)&z1,      g_z1);
    cudaGetSymbolAddress((void**)&z2,      g_z2);
    cudaGetSymbolAddress((void**)&h2,      g_h2);
    cudaGetSymbolAddress((void**)&dp,      g_dp);
    cudaGetSymbolAddress((void**)&dz2,     g_dz2);
    cudaGetSymbolAddress((void**)&dz1,     g_dz1);
    cudaGetSymbolAddress((void**)&alr,     g_alr);
    cudaGetSymbolAddress((void**)&gw_part, g_gw_part);
    cudaGetSymbolAddress((void**)&gb_part, g_gb_part);
    cudaGetSymbolAddress((void**)&gW,      g_gW);
    cudaGetSymbolAddress((void**)&gb,      g_gb);
    cudaGetSymbolAddress((void**)&nW,      g_nW);
    cudaGetSymbolAddress((void**)&nb,      g_nb);

    const dim3 gridG(4, 512);
    const dim3 gridW(4, 4, KSPLIT);

    // projections
    gemm_k<0, false><<<gridG, 256>>>(x, Wk, nullptr, nullptr, nullptr, keys, nullptr);
    gemm_k<0, false><<<gridG, 256>>>(x, Wq, nullptr, nullptr, nullptr, queries, nullptr);
    gemm_k<0, false><<<gridG, 256>>>(x, Wv, nullptr, nullptr, nullptr, values, nullptr);
    alr_k<<<NTOK / 8, 256>>>(x, Wlr, blr, alr);

    // forward (keys) through 2 residual SiLU layers
    gemm_k<1, false><<<gridG, 256>>>(keys, Ws,      bs,     nullptr, nullptr, z1, h1);
    gemm_k<1, false><<<gridG, 256>>>(h1,   Ws + DD, bs + D, nullptr, nullptr, z2, h2);

    // loss grad at preds, dz2
    dp_k<<<ND / 256, 256>>>(h2, values, z2, alr, dp, dz2);

    // gW1 = h1^T @ dz2 ; gb1 = colsum(dz2)
    gw_gemm_k<<<gridW, 256>>>(h1, dz2, gw_part);
    gw_red_k<<<DD / 256, 256>>>(gw_part, gW + DD);
    colsum_part_k<<<256, 256>>>(dz2, gb_part);
    colsum_red_k<<<1, 256>>>(gb_part, gb + D);

    // dz1 = (dp + dz2 @ W1^T) * silu'(z1)
    gemm_k<2, true><<<gridG, 256>>>(dz2, Ws + DD, nullptr, dp, z1, dz1, nullptr);

    // gW0 = keys^T @ dz1 ; gb0 = colsum(dz1)
    gw_gemm_k<<<gridW, 256>>>(keys, dz1, gw_part);
    gw_red_k<<<DD / 256, 256>>>(gw_part, gW);
    colsum_part_k<<<256, 256>>>(dz1, gb_part);
    colsum_red_k<<<1, 256>>>(gb_part, gb);

    // AdamW update + emit -grads
    adamw_k<<<(2 * DD + 2 * D + 255) / 256, 256>>>(Ws, bs, gW, gb, nW, nb, out);

    // retrieved = forward(queries) with updated weights (reuse z1/h1/z2 scratch)
    gemm_k<1, false><<<gridG, 256>>>(queries, nW,      nb,     nullptr, nullptr, z1, h1);
    gemm_k<1, false><<<gridG, 256>>>(h1,      nW + DD, nb + D, nullptr, nullptr, z2, out);
}

// round 3
// speedup vs baseline: 1.6281x; 1.6281x over previous
#include <cuda_runtime.h>
#include <cuda_bf16.h>
#include <math.h>
#include <stdint.h>

#define D      256
#define NTOK   32768
#define ND     (NTOK * D)
#define DD     (D * D)
#define LRc    1e-3f
#define WDc    1e-2f
#define EPSc   1e-8f
#define NSPLIT 64           // split-K partitions for weight grads

// ---------------- scratch (device globals: allocation-free) ----------------
__device__ __nv_bfloat16 g_xbh[ND],  g_xbl[ND];
__device__ __nv_bfloat16 g_keysh[ND], g_keysl[ND], g_keysth[ND], g_keystl[ND];
__device__ __nv_bfloat16 g_qh[ND],   g_ql[ND];
__device__ __nv_bfloat16 g_h1h[ND],  g_h1l[ND],  g_h1th[ND], g_h1tl[ND];
__device__ __nv_bfloat16 g_dz2h[ND], g_dz2l[ND], g_dz2th[ND], g_dz2tl[ND];
__device__ __nv_bfloat16 g_dz1th[ND], g_dz1tl[ND];
__device__ __nv_bfloat16 g_h1qh[ND], g_h1ql[ND];
__device__ __nv_bfloat16 g_wbh[6 * DD], g_wbl[6 * DD];
__device__ __nv_bfloat16 g_nwth[2 * DD], g_nwtl[2 * DD];
__device__ float g_values[ND], g_z1[ND], g_dp[ND];
__device__ float g_part[NSPLIT * DD];
__device__ float g_gW[2 * DD], g_gb[2 * D], g_nb[2 * D], g_alr[NTOK];

__device__ __forceinline__ float sigm(float z) { return 1.0f / (1.0f + expf(-z)); }

__device__ __forceinline__ uint32_t smem_u32(const void* p) {
    uint32_t a;
    asm("{ .reg .u64 t; cvta.to.shared.u64 t, %1; cvt.u32.u64 %0, t; }"
        : "=r"(a) : "l"(p));
    return a;
}

__device__ __forceinline__ void cp16(uint32_t dst, const void* src) {
    asm volatile("cp.async.cg.shared.global [%0], [%1], 16;"
                 :: "r"(dst), "l"(src) : "memory");
}
__device__ __forceinline__ void cp_commit() {
    asm volatile("cp.async.commit_group;" ::: "memory");
}
template <int N>
__device__ __forceinline__ void cp_wait() {
    asm volatile("cp.async.wait_group %0;" :: "n"(N) : "memory");
}

__device__ __forceinline__ void ldsm4(uint32_t* r, uint32_t a) {
    asm volatile("ldmatrix.sync.aligned.m8n8.x4.shared.b16 {%0,%1,%2,%3}, [%4];"
                 : "=r"(r[0]), "=r"(r[1]), "=r"(r[2]), "=r"(r[3]) : "r"(a));
}
__device__ __forceinline__ void ldsm2(uint32_t* r, uint32_t a) {
    asm volatile("ldmatrix.sync.aligned.m8n8.x2.shared.b16 {%0,%1}, [%2];"
                 : "=r"(r[0]), "=r"(r[1]) : "r"(a));
}

__device__ __forceinline__ void mma16816(float* c, const uint32_t* a, const uint32_t* b) {
    asm volatile(
        "mma.sync.aligned.m16n8k16.row.col.f32.bf16.bf16.f32 "
        "{%0,%1,%2,%3}, {%4,%5,%6,%7}, {%8,%9}, {%0,%1,%2,%3};"
        : "+f"(c[0]), "+f"(c[1]), "+f"(c[2]), "+f"(c[3])
        : "r"(a[0]), "r"(a[1]), "r"(a[2]), "r"(a[3]), "r"(b[0]), "r"(b[1]));
}

__device__ __forceinline__ void store_pair(__nv_bfloat16* oh, __nv_bfloat16* ol,
                                           long idx, float v) {
    __nv_bfloat16 h = __float2bfloat16(v);
    oh[idx] = h;
    ol[idx] = __float2bfloat16(v - __bfloat162float(h));
}

// ---------------- epilogue transforms ---------------------------------------
// TF: 0=raw 1=z(+bias) 2=h(resid silu) 3=d(loss grad) 4=dz2 5=dz1
template <int TF>
__device__ __forceinline__ float2 xf(float v0, float v1, int R, int C,
    const __nv_bfloat16* __restrict__ Ahi, const __nv_bfloat16* __restrict__ Alo,
    const float* __restrict__ bias, const float* __restrict__ e0,
    const float* __restrict__ e1, const float* __restrict__ alr_)
{
    if (TF == 0) return make_float2(v0, v1);
    if (TF == 5) {
        float2 ed = *reinterpret_cast<const float2*>(e0 + (size_t)R * 256 + C);
        float2 ez = *reinterpret_cast<const float2*>(e1 + (size_t)R * 256 + C);
        float dh0 = ed.x + v0, dh1 = ed.y + v1;
        float s0 = sigm(ez.x), s1 = sigm(ez.y);
        return make_float2(dh0 * s0 * (1.f + ez.x * (1.f - s0)),
                           dh1 * s1 * (1.f + ez.y * (1.f - s1)));
    }
    float z0 = v0 + bias[C], z1v = v1 + bias[C + 1];
    if (TF == 1) return make_float2(z0, z1v);
    float s0 = sigm(z0), s1 = sigm(z1v);
    __nv_bfloat162 ah = *reinterpret_cast<const __nv_bfloat162*>(Ahi + (size_t)R * 256 + C);
    __nv_bfloat162 al = *reinterpret_cast<const __nv_bfloat162*>(Alo + (size_t)R * 256 + C);
    float a0 = __bfloat162float(ah.x) + __bfloat162float(al.x);
    float a1 = __bfloat162float(ah.y) + __bfloat162float(al.y);
    float h0 = a0 + z0 * s0, h1v = a1 + z1v * s1;
    if (TF == 2) return make_float2(h0, h1v);
    float cf = alr_[R] * 0.0078125f;   // alr * 2/256
    float2 e = *reinterpret_cast<const float2*>(e0 + (size_t)R * 256 + C);
    float d0 = cf * (h0 - e.x), d1 = cf * (h1v - e.y);
    if (TF == 3) return make_float2(d0, d1);
    return make_float2(d0 * s0 * (1.f + z0 * (1.f - s0)),
                       d1 * s1 * (1.f + z1v * (1.f - s1)));
}

#define EPI_ARGS float (&acc)[4][4][4], char* sm, int m0, int n0, int warpR, int warpC, \
    int lane, int tid, const __nv_bfloat16* __restrict__ Ahi, \
    const __nv_bfloat16* __restrict__ Alo, const float* __restrict__ bias, \
    const float* __restrict__ e0, const float* __restrict__ e1, \
    const float* __restrict__ alr_

// normal-layout bf16 hi/lo store, smem-staged, coalesced
template <int TF>
__device__ __forceinline__ void passN(EPI_ARGS,
    __nv_bfloat16* __restrict__ ohi, __nv_bfloat16* __restrict__ olo)
{
    __syncthreads();
    uint32_t* s0 = (uint32_t*)sm;
    uint32_t* s1 = (uint32_t*)(sm + 34816);
    #pragma unroll
    for (int mt = 0; mt < 4; ++mt)
        #pragma unroll
        for (int h = 0; h < 2; ++h) {
            const int rl = warpR * 64 + mt * 16 + (lane >> 2) + h * 8;
            const int R = m0 + rl;
            #pragma unroll
            for (int nt = 0; nt < 4; ++nt) {
                const int cl = warpC * 32 + nt * 8 + 2 * (lane & 3);
                float2 t = xf<TF>(acc[mt][nt][2 * h], acc[mt][nt][2 * h + 1],
                                  R, n0 + cl, Ahi, Alo, bias, e0, e1, alr_);
                __nv_bfloat16 bh0 = __float2bfloat16(t.x), bh1 = __float2bfloat16(t.y);
                __nv_bfloat16 bl0 = __float2bfloat16(t.x - __bfloat162float(bh0));
                __nv_bfloat16 bl1 = __float2bfloat16(t.y - __bfloat162float(bh1));
                const int w = rl * 68 + (cl >> 1);
                s0[w] = (uint32_t)__bfloat16_as_ushort(bh0)
                      | ((uint32_t)__bfloat16_as_ushort(bh1) << 16);
                s1[w] = (uint32_t)__bfloat16_as_ushort(bl0)
                      | ((uint32_t)__bfloat16_as_ushort(bl1) << 16);
            }
        }
    __syncthreads();
    #pragma unroll
    for (int it = 0; it < 8; ++it) {
        const int row = it * 16 + (tid >> 4), seg = tid & 15;
        uint4 vh = *(uint4*)(sm + row * 272 + seg * 16);
        uint4 vl = *(uint4*)(sm + 34816 + row * 272 + seg * 16);
        *(uint4*)(ohi + (size_t)(m0 + row) * 256 + n0 + seg * 8) = vh;
        *(uint4*)(olo + (size_t)(m0 + row) * 256 + n0 + seg * 8) = vl;
    }
}

// transposed-layout bf16 hi/lo store ([feature][token]), smem-staged
template <int TF>
__device__ __forceinline__ void passT(EPI_ARGS,
    __nv_bfloat16* __restrict__ othi, __nv_bfloat16* __restrict__ otlo)
{
    __syncthreads();
    __nv_bfloat16* s0 = (__nv_bfloat16*)sm;
    __nv_bfloat16* s1 = (__nv_bfloat16*)(sm + 34816);
    #pragma unroll
    for (int mt = 0; mt < 4; ++mt)
        #pragma unroll
        for (int h = 0; h < 2; ++h) {
            const int rl = warpR * 64 + mt * 16 + (lane >> 2) + h * 8;
            const int R = m0 + rl;
            #pragma unroll
            for (int nt = 0; nt < 4; ++nt) {
                const int cl = warpC * 32 + nt * 8 + 2 * (lane & 3);
                float2 t = xf<TF>(acc[mt][nt][2 * h], acc[mt][nt][2 * h + 1],
                                  R, n0 + cl, Ahi, Alo, bias, e0, e1, alr_);
                __nv_bfloat16 bh0 = __float2bfloat16(t.x), bh1 = __float2bfloat16(t.y);
                s0[cl * 136 + rl]       = bh0;
                s0[(cl + 1) * 136 + rl] = bh1;
                s1[cl * 136 + rl]       = __float2bfloat16(t.x - __bfloat162float(bh0));
                s1[(cl + 1) * 136 + rl] = __float2bfloat16(t.y - __bfloat162float(bh1));
            }
        }
    __syncthreads();
    #pragma unroll
    for (int it = 0; it < 8; ++it) {
        const int c = it * 16 + (tid >> 4), seg = tid & 15;
        uint4 vh = *(uint4*)(sm + c * 272 + seg * 16);
        uint4 vl = *(uint4*)(sm + 34816 + c * 272 + seg * 16);
        *(uint4*)(othi + (size_t)(n0 + c) * 32768 + m0 + seg * 8) = vh;
        *(uint4*)(otlo + (size_t)(n0 + c) * 32768 + m0 + seg * 8) = vl;
    }
}

// fp32 store, smem-staged
template <int TF>
__device__ __forceinline__ void passF(EPI_ARGS, float* __restrict__ f0)
{
    __syncthreads();
    #pragma unroll
    for (int mt = 0; mt < 4; ++mt)
        #pragma unroll
        for (int h = 0; h < 2; ++h) {
            const int rl = warpR * 64 + mt * 16 + (lane >> 2) + h * 8;
            const int R = m0 + rl;
            #pragma unroll
            for (int nt = 0; nt < 4; ++nt) {
                const int cl = warpC * 32 + nt * 8 + 2 * (lane & 3);
                float2 t = xf<TF>(acc[mt][nt][2 * h], acc[mt][nt][2 * h + 1],
                                  R, n0 + cl, Ahi, Alo, bias, e0, e1, alr_);
                *(float2*)(sm + rl * 528 + cl * 4) = t;
            }
        }
    __syncthreads();
    #pragma unroll
    for (int it = 0; it < 16; ++it) {
        const int row = it * 8 + (tid >> 5), seg = tid & 31;
        uint4 v = *(uint4*)(sm + row * 528 + seg * 16);
        *(uint4*)(f0 + (size_t)(m0 + row) * 256 + n0 + seg * 4) = v;
    }
}

// ---------------- mma.sync GEMM: C[128 x 128] tile, 3-term bf16 split -------
enum { M_PROJ = 0, M_PROJ_T, M_VAL, M_FWD_KT, M_FWD_Q, M_FWD_OUT, M_DZ2, M_DZ1, M_PART };

#define SMEM_BYTES 81920

template <int MODE>
__global__ __launch_bounds__(256, 2) void mm_k(
    const __nv_bfloat16* __restrict__ Ahi, const __nv_bfloat16* __restrict__ Alo, long lda,
    const __nv_bfloat16* __restrict__ Bhi, const __nv_bfloat16* __restrict__ Blo, long ldb,
    const float* __restrict__ bias, const float* __restrict__ e0,
    const float* __restrict__ e1, const float* __restrict__ alr_,
    float* __restrict__ f0,
    __nv_bfloat16* __restrict__ ohi, __nv_bfloat16* __restrict__ olo,
    __nv_bfloat16* __restrict__ othi, __nv_bfloat16* __restrict__ otlo,
    int nck)
{
    extern __shared__ char sm[];
    const int tid = threadIdx.x, lane = tid & 31, wid = tid >> 5;
    const int warpR = wid >> 2, warpC = wid & 3;
    const int m0 = blockIdx.y * 128, n0 = blockIdx.x * 128;
    const long kbase = (long)blockIdx.z * nck * 32;
    const uint32_t sb = smem_u32(sm);

    float acc[4][4][4];
    #pragma unroll
    for (int i = 0; i < 4; ++i)
        #pragma unroll
        for (int j = 0; j < 4; ++j)
            #pragma unroll
            for (int e = 0; e < 4; ++e) acc[i][j][e] = 0.f;

    // per-lane ldmatrix offsets (80B row stride, conflict-free)
    const uint32_t aoff = (uint32_t)((((lane & 7) + ((lane >> 3) & 1) * 8)) * 80
                                     + (lane >> 4) * 16);
    const int lb = lane & 15;
    const uint32_t boff = (uint32_t)((lb & 7) * 80 + (lb >> 3) * 16);

    #define LOAD_CHUNK(ck, buf) do {                                           \
        const long k0_ = kbase + (long)(ck) * 32;                              \
        const uint32_t sbb_ = sb + (buf) * 40960;                              \
        _Pragma("unroll")                                                      \
        for (int rep = 0; rep < 2; ++rep) {                                    \
            const int id = tid + rep * 256;                                    \
            const int row = id >> 2, seg = id & 3;                             \
            const uint32_t so = row * 80 + seg * 16;                           \
            const long ga = (long)(m0 + row) * lda + k0_ + seg * 8;            \
            const long gbx = (long)(n0 + row) * ldb + k0_ + seg * 8;           \
            cp16(sbb_ + so,          Ahi + ga);                                \
            cp16(sbb_ + 10240 + so,  Alo + ga);                                \
            cp16(sbb_ + 20480 + so,  Bhi + gbx);                               \
            cp16(sbb_ + 30720 + so,  Blo + gbx);                               \
        }                                                                      \
        cp_commit();                                                           \
    } while (0)

    LOAD_CHUNK(0, 0);
    for (int ck = 0; ck < nck; ++ck) {
        if (ck + 1 < nck) { LOAD_CHUNK(ck + 1, (ck + 1) & 1); cp_wait<1>(); }
        else              { cp_wait<0>(); }
        __syncthreads();
        const uint32_t sbb = sb + (ck & 1) * 40960;
        #pragma unroll
        for (int step = 0; step < 2; ++step) {
            uint32_t av[4][4], bh[4][2], bl[4][2];
            #pragma unroll
            for (int mt = 0; mt < 4; ++mt)
                ldsm4(av[mt], sbb + (warpR * 64 + mt * 16) * 80 + step * 32 + aoff);
            #pragma unroll
            for (int nt = 0; nt < 4; ++nt) {
                ldsm2(bh[nt], sbb + 20480 + (warpC * 32 + nt * 8) * 80 + step * 32 + boff);
                ldsm2(bl[nt], sbb + 30720 + (warpC * 32 + nt * 8) * 80 + step * 32 + boff);
            }
            #pragma unroll
            for (int mt = 0; mt < 4; ++mt)
                #pragma unroll
                for (int nt = 0; nt < 4; ++nt)
                    mma16816(acc[mt][nt], av[mt], bh[nt]);
            #pragma unroll
            for (int mt = 0; mt < 4; ++mt)
                #pragma unroll
                for (int nt = 0; nt < 4; ++nt)
                    mma16816(acc[mt][nt], av[mt], bl[nt]);
            #pragma unroll
            for (int mt = 0; mt < 4; ++mt)
                ldsm4(av[mt], sbb + 10240 + (warpR * 64 + mt * 16) * 80 + step * 32 + aoff);
            #pragma unroll
            for (int mt = 0; mt < 4; ++mt)
                #pragma unroll
                for (int nt = 0; nt < 4; ++nt)
                    mma16816(acc[mt][nt], av[mt], bh[nt]);
        }
        __syncthreads();
    }
    #undef LOAD_CHUNK

    #define EPI acc, sm, m0, n0, warpR, warpC, lane, tid, Ahi, Alo, bias, e0, e1, alr_
    if (MODE == M_PROJ) {
        passN<0>(EPI, ohi, olo);
    } else if (MODE == M_PROJ_T) {
        passN<0>(EPI, ohi, olo);
        passT<0>(EPI, othi, otlo);
    } else if (MODE == M_VAL) {
        passF<0>(EPI, f0);
    } else if (MODE == M_FWD_KT) {
        passF<1>(EPI, f0);                 // z1
        passN<2>(EPI, ohi, olo);           // h1
        passT<2>(EPI, othi, otlo);         // h1^T
    } else if (MODE == M_FWD_Q) {
        passN<2>(EPI, ohi, olo);
    } else if (MODE == M_FWD_OUT) {
        passF<2>(EPI, f0);
    } else if (MODE == M_DZ2) {
        passF<3>(EPI, f0);                 // dp
        passN<4>(EPI, ohi, olo);           // dz2
        passT<4>(EPI, othi, otlo);         // dz2^T
    } else if (MODE == M_DZ1) {
        passT<5>(EPI, othi, otlo);         // dz1^T
    } else {                               // M_PART: split-K partial
        passF<0>(EPI, f0 + (size_t)blockIdx.z * DD);
    }
    #undef EPI
}

// ---------------- x split + adaptive lr (fused) -----------------------------
__global__ void xsplit_alr(const float* __restrict__ x, const float* __restrict__ Wlr,
                           const float* __restrict__ blr,
                           __nv_bfloat16* __restrict__ xh, __nv_bfloat16* __restrict__ xl,
                           float* __restrict__ alr)
{
    const int tok = blockIdx.x;
    const int j = threadIdx.x;
    const long idx = (long)tok * 256 + j;
    const float v = x[idx];
    __nv_bfloat16 h = __float2bfloat16(v);
    xh[idx] = h;
    xl[idx] = __float2bfloat16(v - __bfloat162float(h));

    float s = v * Wlr[j];
    #pragma unroll
    for (int o = 16; o > 0; o >>= 1) s += __shfl_xor_sync(0xffffffffu, s, o);
    __shared__ float ws[8];
    if ((j & 31) == 0) ws[j >> 5] = s;
    __syncthreads();
    if (j == 0) {
        float t = 0.0f;
        #pragma unroll
        for (int i = 0; i < 8; ++i) t += ws[i];
        alr[tok] = 0.1f * sigm(t + blr[0]);
    }
}

// ---------------- weight prep: [n][k] bf16 hi/lo -----------------------------
// slots: 0=Wk^T 1=Wq^T 2=Wv^T 3=W0^T 4=W1^T 5=W1
__global__ void wprep(const float* __restrict__ Wk, const float* __restrict__ Wq,
                      const float* __restrict__ Wv, const float* __restrict__ Ws,
                      __nv_bfloat16* __restrict__ wh, __nv_bfloat16* __restrict__ wl)
{
    const int idx = blockIdx.x * 256 + threadIdx.x;
    const int slot = idx >> 16;
    const int r = (idx >> 8) & 255;   // out row (n)
    const int c = idx & 255;          // out col (k)
    float v;
    if      (slot == 0) v = Wk[c * 256 + r];
    else if (slot == 1) v = Wq[c * 256 + r];
    else if (slot == 2) v = Wv[c * 256 + r];
    else if (slot == 3) v = Ws[c * 256 + r];
    else if (slot == 4) v = Ws[DD + c * 256 + r];
    else                v = Ws[DD + r * 256 + c];
    store_pair(wh, wl, idx, v);
}

// ---------------- split-K reduce for weight grads ---------------------------
__global__ void gwred(const float* __restrict__ part, float* __restrict__ gW)
{
    const int i = blockIdx.x * 256 + threadIdx.x;   // 0..DD-1
    float s = 0.0f;
    for (int z = 0; z < NSPLIT; ++z) s += part[(size_t)z * DD + i];
    gW[i] = s;
}

// ---------------- bias grads: row sums of transposed dz ---------------------
__global__ void colsum_t(const __nv_bfloat16* __restrict__ th,
                         const __nv_bfloat16* __restrict__ tl, float* __restrict__ gb)
{
    const int n = blockIdx.x;
    float s = 0.0f;
    for (int t = threadIdx.x; t < 32768; t += 256)
        s += __bfloat162float(th[(size_t)n * 32768 + t])
           + __bfloat162float(tl[(size_t)n * 32768 + t]);
    #pragma unroll
    for (int o = 16; o > 0; o >>= 1) s += __shfl_xor_sync(0xffffffffu, s, o);
    __shared__ float ws[8];
    if ((threadIdx.x & 31) == 0) ws[threadIdx.x >> 5] = s;
    __syncthreads();
    if (threadIdx.x == 0) {
        float t = 0.0f;
        #pragma unroll
        for (int i = 0; i < 8; ++i) t += ws[i];
        gb[n] = t;
    }
}

// ---------------- AdamW step: out(-g), transposed bf16 updated weights ------
__global__ void adamw2(const float* __restrict__ Ws, const float* __restrict__ bs,
                       const float* __restrict__ gW, const float* __restrict__ gb,
                       __nv_bfloat16* __restrict__ nwth, __nv_bfloat16* __restrict__ nwtl,
                       float* __restrict__ nb, float* __restrict__ out)
{
    const int idx = blockIdx.x * 256 + threadIdx.x;
    const float decay = 1.0f - LRc * WDc;
    if (idx < 2 * DD) {
        const float g = gW[idx];
        out[ND + idx] = -g;
        const float nw = Ws[idx] * decay - LRc * g / (fabsf(g) + EPSc);
        const int layer = idx >> 16;
        const int k = (idx >> 8) & 255;
        const int n = idx & 255;
        store_pair(nwth, nwtl, (long)layer * DD + n * 256 + k, nw);
    } else if (idx < 2 * DD + 2 * D) {
        const int b = idx - 2 * DD;
        const float g = gb[b];
        out[ND + 2 * DD + b] = -g;
        nb[b] = bs[b] * decay - LRc * g / (fabsf(g) + EPSc);
    }
}

// ---------------------------------------------------------------------------
extern "C" void kernel_launch(void* const* d_in, const int* in_sizes, int n_in,
                              void* d_out, int out_size)
{
    const float* x   = (const float*)d_in[0];
    const float* Wk  = (const float*)d_in[1];
    const float* Wq  = (const float*)d_in[2];
    const float* Wv  = (const float*)d_in[3];
    const float* Wlr = (const float*)d_in[4];
    const float* blr = (const float*)d_in[5];
    const float* Ws  = (const float*)d_in[6];
    const float* bs  = (const float*)d_in[7];
    float* out = (float*)d_out;

    #define SYM(T, v, s) T* v; cudaGetSymbolAddress((void**)&v, s)
    SYM(__nv_bfloat16, xbh, g_xbh);   SYM(__nv_bfloat16, xbl, g_xbl);
    SYM(__nv_bfloat16, keysh, g_keysh); SYM(__nv_bfloat16, keysl, g_keysl);
    SYM(__nv_bfloat16, keysth, g_keysth); SYM(__nv_bfloat16, keystl, g_keystl);
    SYM(__nv_bfloat16, qh, g_qh);     SYM(__nv_bfloat16, ql, g_ql);
    SYM(__nv_bfloat16, h1h, g_h1h);   SYM(__nv_bfloat16, h1l, g_h1l);
    SYM(__nv_bfloat16, h1th, g_h1th); SYM(__nv_bfloat16, h1tl, g_h1tl);
    SYM(__nv_bfloat16, dz2h, g_dz2h); SYM(__nv_bfloat16, dz2l, g_dz2l);
    SYM(__nv_bfloat16, dz2th, g_dz2th); SYM(__nv_bfloat16, dz2tl, g_dz2tl);
    SYM(__nv_bfloat16, dz1th, g_dz1th); SYM(__nv_bfloat16, dz1tl, g_dz1tl);
    SYM(__nv_bfloat16, h1qh, g_h1qh); SYM(__nv_bfloat16, h1ql, g_h1ql);
    SYM(__nv_bfloat16, wbh, g_wbh);   SYM(__nv_bfloat16, wbl, g_wbl);
    SYM(__nv_bfloat16, nwth, g_nwth); SYM(__nv_bfloat16, nwtl, g_nwtl);
    SYM(float, values, g_values); SYM(float, z1, g_z1); SYM(float, dp, g_dp);
    SYM(float, part, g_part); SYM(float, gW, g_gW); SYM(float, gb, g_gb);
    SYM(float, nb, g_nb); SYM(float, alr, g_alr);
    #undef SYM

    #define SETSM(M) cudaFuncSetAttribute(mm_k<M>, \
        cudaFuncAttributeMaxDynamicSharedMemorySize, SMEM_BYTES)
    SETSM(M_PROJ); SETSM(M_PROJ_T); SETSM(M_VAL); SETSM(M_FWD_KT); SETSM(M_FWD_Q);
    SETSM(M_FWD_OUT); SETSM(M_DZ2); SETSM(M_DZ1); SETSM(M_PART);
    #undef SETSM

    const dim3 gridM(2, 256, 1);          // main GEMMs, K=256 (8 chunks)
    const dim3 gridP(2, 2, NSPLIT);       // weight grads, K=512/split (16 chunks)

    xsplit_alr<<<NTOK, 256>>>(x, Wlr, blr, xbh, xbl, alr);
    wprep<<<6 * DD / 256, 256>>>(Wk, Wq, Wv, Ws, wbh, wbl);

    // projections
    mm_k<M_PROJ_T><<<gridM, 256, SMEM_BYTES>>>(xbh, xbl, 256, wbh, wbl, 256,
        nullptr, nullptr, nullptr, nullptr, nullptr, keysh, keysl, keysth, keystl, 8);
    mm_k<M_PROJ><<<gridM, 256, SMEM_BYTES>>>(xbh, xbl, 256, wbh + DD, wbl + DD, 256,
        nullptr, nullptr, nullptr, nullptr, nullptr, qh, ql, nullptr, nullptr, 8);
    mm_k<M_VAL><<<gridM, 256, SMEM_BYTES>>>(xbh, xbl, 256, wbh + 2 * DD, wbl + 2 * DD, 256,
        nullptr, nullptr, nullptr, nullptr, values, nullptr, nullptr, nullptr, nullptr, 8);

    // forward on keys: z1, h1, h1^T
    mm_k<M_FWD_KT><<<gridM, 256, SMEM_BYTES>>>(keysh, keysl, 256, wbh + 3 * DD, wbl + 3 * DD, 256,
        bs, nullptr, nullptr, nullptr, z1, h1h, h1l, h1th, h1tl, 8);
    // dz2 (+dp): z2 recomputed in epilogue
    mm_k<M_DZ2><<<gridM, 256, SMEM_BYTES>>>(h1h, h1l, 256, wbh + 4 * DD, wbl + 4 * DD, 256,
        bs + D, values, nullptr, alr, dp, dz2h, dz2l, dz2th, dz2tl, 8);
    // dz1 = (dp + dz2 @ W1^T) * silu'(z1)
    mm_k<M_DZ1><<<gridM, 256, SMEM_BYTES>>>(dz2h, dz2l, 256, wbh + 5 * DD, wbl + 5 * DD, 256,
        nullptr, dp, z1, nullptr, nullptr, nullptr, nullptr, dz1th, dz1tl, 8);

    // gW1 = h1^T @ dz2 ; gW0 = keys^T @ dz1 (deterministic split-K)
    mm_k<M_PART><<<gridP, 256, SMEM_BYTES>>>(h1th, h1tl, 32768, dz2th, dz2tl, 32768,
        nullptr, nullptr, nullptr, nullptr, part, nullptr, nullptr, nullptr, nullptr, 16);
    gwred<<<DD / 256, 256>>>(part, gW + DD);
    mm_k<M_PART><<<gridP, 256, SMEM_BYTES>>>(keysth, keystl, 32768, dz1th, dz1tl, 32768,
        nullptr, nullptr, nullptr, nullptr, part, nullptr, nullptr, nullptr, nullptr, 16);
    gwred<<<DD / 256, 256>>>(part, gW);

    // bias grads
    colsum_t<<<256, 256>>>(dz2th, dz2tl, gb + D);
    colsum_t<<<256, 256>>>(dz1th, dz1tl, gb);

    // AdamW update + emit -grads + transposed bf16 updated weights
    adamw2<<<(2 * DD + 2 * D + 255) / 256, 256>>>(Ws, bs, gW, gb, nwth, nwtl, nb, out);

    // retrieved = forward(queries) with updated weights
    mm_k<M_FWD_Q><<<gridM, 256, SMEM_BYTES>>>(qh, ql, 256, nwth, nwtl, 256,
        nb, nullptr, nullptr, nullptr, nullptr, h1qh, h1ql, nullptr, nullptr, 8);
    mm_k<M_FWD_OUT><<<gridM, 256, SMEM_BYTES>>>(h1qh, h1ql, 256, nwth + DD, nwtl + DD, 256,
        nb + D, nullptr, nullptr, nullptr, out, nullptr, nullptr, nullptr, nullptr, 8);
}

// round 4
// speedup vs baseline: 1.7663x; 1.0849x over previous
#include <cuda_runtime.h>
#include <cuda_bf16.h>
#include <math.h>
#include <stdint.h>

#define D      256
#define NTOK   32768
#define ND     (NTOK * D)
#define DD     (D * D)
#define LRc    1e-3f
#define WDc    1e-2f
#define EPSc   1e-8f

// ---------------- scratch (device globals: allocation-free) ----------------
__device__ __nv_bfloat16 g_xbh[ND],  g_xbl[ND];
__device__ __nv_bfloat16 g_keysh[ND], g_keysl[ND], g_keysth[ND], g_keystl[ND];
__device__ __nv_bfloat16 g_qh[ND],   g_ql[ND];
__device__ __nv_bfloat16 g_h1h[ND],  g_h1l[ND],  g_h1th[ND], g_h1tl[ND];
__device__ __nv_bfloat16 g_dz2h[ND], g_dz2l[ND], g_dz2th[ND], g_dz2tl[ND];
__device__ __nv_bfloat16 g_dz1th[ND], g_dz1tl[ND];
__device__ __nv_bfloat16 g_h1qh[ND], g_h1ql[ND];
__device__ __nv_bfloat16 g_wbh[6 * DD], g_wbl[6 * DD];
__device__ __nv_bfloat16 g_nwth[2 * DD], g_nwtl[2 * DD];
__device__ float g_values[ND], g_z1[ND], g_dp[ND];
__device__ float g_part[128 * DD];
__device__ float g_gbp[2 * 256 * 256];
__device__ float g_gW[2 * DD], g_gb[2 * D], g_nb[2 * D], g_alr[NTOK];

__device__ __forceinline__ float sigm(float z) { return 1.0f / (1.0f + expf(-z)); }

__device__ __forceinline__ uint32_t smem_u32(const void* p) {
    uint32_t a;
    asm("{ .reg .u64 t; cvta.to.shared.u64 t, %1; cvt.u32.u64 %0, t; }"
        : "=r"(a) : "l"(p));
    return a;
}

__device__ __forceinline__ void cp16(uint32_t dst, const void* src) {
    asm volatile("cp.async.cg.shared.global [%0], [%1], 16;"
                 :: "r"(dst), "l"(src) : "memory");
}
__device__ __forceinline__ void cp_commit() {
    asm volatile("cp.async.commit_group;" ::: "memory");
}
template <int N>
__device__ __forceinline__ void cp_wait() {
    asm volatile("cp.async.wait_group %0;" :: "n"(N) : "memory");
}

__device__ __forceinline__ void ldsm4(uint32_t* r, uint32_t a) {
    asm volatile("ldmatrix.sync.aligned.m8n8.x4.shared.b16 {%0,%1,%2,%3}, [%4];"
                 : "=r"(r[0]), "=r"(r[1]), "=r"(r[2]), "=r"(r[3]) : "r"(a));
}
__device__ __forceinline__ void ldsm2(uint32_t* r, uint32_t a) {
    asm volatile("ldmatrix.sync.aligned.m8n8.x2.shared.b16 {%0,%1}, [%2];"
                 : "=r"(r[0]), "=r"(r[1]) : "r"(a));
}

__device__ __forceinline__ void mma16816(float* c, const uint32_t* a, const uint32_t* b) {
    asm volatile(
        "mma.sync.aligned.m16n8k16.row.col.f32.bf16.bf16.f32 "
        "{%0,%1,%2,%3}, {%4,%5,%6,%7}, {%8,%9}, {%0,%1,%2,%3};"
        : "+f"(c[0]), "+f"(c[1]), "+f"(c[2]), "+f"(c[3])
        : "r"(a[0]), "r"(a[1]), "r"(a[2]), "r"(a[3]), "r"(b[0]), "r"(b[1]));
}

__device__ __forceinline__ void store_pair(__nv_bfloat16* oh, __nv_bfloat16* ol,
                                           long idx, float v) {
    __nv_bfloat16 h = __float2bfloat16(v);
    oh[idx] = h;
    ol[idx] = __float2bfloat16(v - __bfloat162float(h));
}

// ---------------- epilogue transforms ---------------------------------------
// TF: 0=raw 1=z(+bias) 2=h(resid silu) 3=d(loss grad) 4=dz2 5=dz1
template <int TF>
__device__ __forceinline__ float2 xf(float v0, float v1, int R, int C,
    const __nv_bfloat16* __restrict__ Ahi, const __nv_bfloat16* __restrict__ Alo,
    const float* __restrict__ bias, const float* __restrict__ e0,
    const float* __restrict__ e1, const float* __restrict__ alr_)
{
    if (TF == 0) return make_float2(v0, v1);
    if (TF == 5) {
        float2 ed = *reinterpret_cast<const float2*>(e0 + (size_t)R * 256 + C);
        float2 ez = *reinterpret_cast<const float2*>(e1 + (size_t)R * 256 + C);
        float dh0 = ed.x + v0, dh1 = ed.y + v1;
        float s0 = sigm(ez.x), s1 = sigm(ez.y);
        return make_float2(dh0 * s0 * (1.f + ez.x * (1.f - s0)),
                           dh1 * s1 * (1.f + ez.y * (1.f - s1)));
    }
    float z0 = v0 + bias[C], z1v = v1 + bias[C + 1];
    if (TF == 1) return make_float2(z0, z1v);
    float s0 = sigm(z0), s1 = sigm(z1v);
    __nv_bfloat162 ah = *reinterpret_cast<const __nv_bfloat162*>(Ahi + (size_t)R * 256 + C);
    __nv_bfloat162 al = *reinterpret_cast<const __nv_bfloat162*>(Alo + (size_t)R * 256 + C);
    float a0 = __bfloat162float(ah.x) + __bfloat162float(al.x);
    float a1 = __bfloat162float(ah.y) + __bfloat162float(al.y);
    float h0 = a0 + z0 * s0, h1v = a1 + z1v * s1;
    if (TF == 2) return make_float2(h0, h1v);
    float cf = alr_[R] * 0.0078125f;   // alr * 2/256
    float2 e = *reinterpret_cast<const float2*>(e0 + (size_t)R * 256 + C);
    float d0 = cf * (h0 - e.x), d1 = cf * (h1v - e.y);
    if (TF == 3) return make_float2(d0, d1);
    return make_float2(d0 * s0 * (1.f + z0 * (1.f - s0)),
                       d1 * s1 * (1.f + z1v * (1.f - s1)));
}

#define EPI_ARGS float (&acc)[4][4][4], char* sm, int m0, int n0, int warpR, int warpC, \
    int lane, int tid, const __nv_bfloat16* __restrict__ Ahi, \
    const __nv_bfloat16* __restrict__ Alo, const float* __restrict__ bias, \
    const float* __restrict__ e0, const float* __restrict__ e1, \
    const float* __restrict__ alr_

// normal-layout bf16 hi/lo store, smem-staged, coalesced
template <int TF>
__device__ __forceinline__ void passN(EPI_ARGS,
    __nv_bfloat16* __restrict__ ohi, __nv_bfloat16* __restrict__ olo)
{
    __syncthreads();
    uint32_t* s0 = (uint32_t*)sm;
    uint32_t* s1 = (uint32_t*)(sm + 34816);
    #pragma unroll
    for (int mt = 0; mt < 4; ++mt)
        #pragma unroll
        for (int h = 0; h < 2; ++h) {
            const int rl = warpR * 64 + mt * 16 + (lane >> 2) + h * 8;
            const int R = m0 + rl;
            #pragma unroll
            for (int nt = 0; nt < 4; ++nt) {
                const int cl = warpC * 32 + nt * 8 + 2 * (lane & 3);
                float2 t = xf<TF>(acc[mt][nt][2 * h], acc[mt][nt][2 * h + 1],
                                  R, n0 + cl, Ahi, Alo, bias, e0, e1, alr_);
                __nv_bfloat16 bh0 = __float2bfloat16(t.x), bh1 = __float2bfloat16(t.y);
                __nv_bfloat16 bl0 = __float2bfloat16(t.x - __bfloat162float(bh0));
                __nv_bfloat16 bl1 = __float2bfloat16(t.y - __bfloat162float(bh1));
                const int w = rl * 68 + (cl >> 1);
                s0[w] = (uint32_t)__bfloat16_as_ushort(bh0)
                      | ((uint32_t)__bfloat16_as_ushort(bh1) << 16);
                s1[w] = (uint32_t)__bfloat16_as_ushort(bl0)
                      | ((uint32_t)__bfloat16_as_ushort(bl1) << 16);
            }
        }
    __syncthreads();
    #pragma unroll
    for (int it = 0; it < 8; ++it) {
        const int row = it * 16 + (tid >> 4), seg = tid & 15;
        uint4 vh = *(uint4*)(sm + row * 272 + seg * 16);
        uint4 vl = *(uint4*)(sm + 34816 + row * 272 + seg * 16);
        *(uint4*)(ohi + (size_t)(m0 + row) * 256 + n0 + seg * 8) = vh;
        *(uint4*)(olo + (size_t)(m0 + row) * 256 + n0 + seg * 8) = vl;
    }
}

// transposed-layout bf16 hi/lo store ([feature][token]), smem-staged
template <int TF>
__device__ __forceinline__ void passT(EPI_ARGS,
    __nv_bfloat16* __restrict__ othi, __nv_bfloat16* __restrict__ otlo)
{
    __syncthreads();
    __nv_bfloat16* s0 = (__nv_bfloat16*)sm;
    __nv_bfloat16* s1 = (__nv_bfloat16*)(sm + 34816);
    #pragma unroll
    for (int mt = 0; mt < 4; ++mt)
        #pragma unroll
        for (int h = 0; h < 2; ++h) {
            const int rl = warpR * 64 + mt * 16 + (lane >> 2) + h * 8;
            const int R = m0 + rl;
            #pragma unroll
            for (int nt = 0; nt < 4; ++nt) {
                const int cl = warpC * 32 + nt * 8 + 2 * (lane & 3);
                float2 t = xf<TF>(acc[mt][nt][2 * h], acc[mt][nt][2 * h + 1],
                                  R, n0 + cl, Ahi, Alo, bias, e0, e1, alr_);
                __nv_bfloat16 bh0 = __float2bfloat16(t.x), bh1 = __float2bfloat16(t.y);
                s0[cl * 136 + rl]       = bh0;
                s0[(cl + 1) * 136 + rl] = bh1;
                s1[cl * 136 + rl]       = __float2bfloat16(t.x - __bfloat162float(bh0));
                s1[(cl + 1) * 136 + rl] = __float2bfloat16(t.y - __bfloat162float(bh1));
            }
        }
    __syncthreads();
    #pragma unroll
    for (int it = 0; it < 8; ++it) {
        const int c = it * 16 + (tid >> 4), seg = tid & 15;
        uint4 vh = *(uint4*)(sm + c * 272 + seg * 16);
        uint4 vl = *(uint4*)(sm + 34816 + c * 272 + seg * 16);
        *(uint4*)(othi + (size_t)(n0 + c) * 32768 + m0 + seg * 8) = vh;
        *(uint4*)(otlo + (size_t)(n0 + c) * 32768 + m0 + seg * 8) = vl;
    }
}

// bias-grad partial: column sums of the transposed tile still staged in smem.
// gbp layout: [mtile(256)][feature(256)]
__device__ __forceinline__ void biasPart(char* sm, int m0, int n0, int tid,
                                         float* __restrict__ gbp)
{
    const int c = tid & 127, half = tid >> 7;
    const char* p0 = sm + c * 272 + half * 128;          // 64 tokens = 128 bytes
    const char* p1 = sm + 34816 + c * 272 + half * 128;
    float s = 0.f;
    #pragma unroll
    for (int i = 0; i < 8; ++i) {
        uint4 v0 = *(const uint4*)(p0 + i * 16);
        uint4 v1 = *(const uint4*)(p1 + i * 16);
        const uint32_t* w0 = (const uint32_t*)&v0;
        const uint32_t* w1 = (const uint32_t*)&v1;
        #pragma unroll
        for (int k = 0; k < 4; ++k) {
            __nv_bfloat162 a = *(const __nv_bfloat162*)&w0[k];
            __nv_bfloat162 b = *(const __nv_bfloat162*)&w1[k];
            s += __bfloat162float(a.x) + __bfloat162float(a.y)
               + __bfloat162float(b.x) + __bfloat162float(b.y);
        }
    }
    float* tmp = (float*)(sm + 70656);
    tmp[tid] = s;
    __syncthreads();
    if (tid < 128)
        gbp[(m0 >> 7) * 256 + n0 + tid] = tmp[tid] + tmp[tid + 128];
}

// fp32 store, smem-staged
template <int TF>
__device__ __forceinline__ void passF(EPI_ARGS, float* __restrict__ f0)
{
    __syncthreads();
    #pragma unroll
    for (int mt = 0; mt < 4; ++mt)
        #pragma unroll
        for (int h = 0; h < 2; ++h) {
            const int rl = warpR * 64 + mt * 16 + (lane >> 2) + h * 8;
            const int R = m0 + rl;
            #pragma unroll
            for (int nt = 0; nt < 4; ++nt) {
                const int cl = warpC * 32 + nt * 8 + 2 * (lane & 3);
                float2 t = xf<TF>(acc[mt][nt][2 * h], acc[mt][nt][2 * h + 1],
                                  R, n0 + cl, Ahi, Alo, bias, e0, e1, alr_);
                *(float2*)(sm + rl * 528 + cl * 4) = t;
            }
        }
    __syncthreads();
    #pragma unroll
    for (int it = 0; it < 16; ++it) {
        const int row = it * 8 + (tid >> 5), seg = tid & 31;
        uint4 v = *(uint4*)(sm + row * 528 + seg * 16);
        *(uint4*)(f0 + (size_t)(m0 + row) * 256 + n0 + seg * 4) = v;
    }
}

// ---------------- mma.sync GEMM: C[128 x 128] tile, 3-term bf16 split -------
enum { M_PROJ3 = 0, M_FWD_KT, M_FWD_Q, M_FWD_OUT, M_DZ2, M_DZ1, M_PART2 };

#define SMEM_BYTES 81920

struct MMArgs {
    const __nv_bfloat16 *Ah, *Al, *Bh, *Bl;
    const __nv_bfloat16 *A2h, *A2l, *B2h, *B2l;      // PART2 second pair
    long lda, ldb;
    const float *bias, *e0, *e1, *alr;
    float *f0, *gbp;
    __nv_bfloat16 *ohi, *olo, *othi, *otlo, *o2h, *o2l;
    int nck;
};

template <int MODE>
__global__ __launch_bounds__(256, 2) void mm_k(const MMArgs a)
{
    extern __shared__ char sm[];
    const int tid = threadIdx.x, lane = tid & 31, wid = tid >> 5;
    const int warpR = wid >> 2, warpC = wid & 3;
    const int m0 = blockIdx.y * 128;
    const int n0 = (MODE == M_PROJ3 ? (blockIdx.x & 1) * 128 : blockIdx.x * 128);
    const int nck = a.nck;
    const uint32_t sb = smem_u32(sm);

    const __nv_bfloat16 *Ahi = a.Ah, *Alo = a.Al, *Bhi = a.Bh, *Blo = a.Bl;
    long kbase = 0;
    int slot = 0;
    if (MODE == M_PROJ3) {
        slot = blockIdx.x >> 1;
        Bhi = a.Bh + (size_t)slot * DD;
        Blo = a.Bl + (size_t)slot * DD;
    }
    if (MODE == M_PART2) {
        if (blockIdx.z >= 64) { Ahi = a.A2h; Alo = a.A2l; Bhi = a.B2h; Blo = a.B2l; }
        kbase = (long)(blockIdx.z & 63) * nck * 32;
    }

    float acc[4][4][4];
    #pragma unroll
    for (int i = 0; i < 4; ++i)
        #pragma unroll
        for (int j = 0; j < 4; ++j)
            #pragma unroll
            for (int e = 0; e < 4; ++e) acc[i][j][e] = 0.f;

    // per-lane ldmatrix offsets (80B row stride, conflict-free)
    const uint32_t aoff = (uint32_t)((((lane & 7) + ((lane >> 3) & 1) * 8)) * 80
                                     + (lane >> 4) * 16);
    const int lb = lane & 15;
    const uint32_t boff = (uint32_t)((lb & 7) * 80 + (lb >> 3) * 16);

    #define LOAD_CHUNK(ck, buf) do {                                           \
        const long k0_ = kbase + (long)(ck) * 32;                              \
        const uint32_t sbb_ = sb + (buf) * 40960;                              \
        _Pragma("unroll")                                                      \
        for (int rep = 0; rep < 2; ++rep) {                                    \
            const int id = tid + rep * 256;                                    \
            const int row = id >> 2, seg = id & 3;                             \
            const uint32_t so = row * 80 + seg * 16;                           \
            const long ga = (long)(m0 + row) * a.lda + k0_ + seg * 8;          \
            const long gbx = (long)(n0 + row) * a.ldb + k0_ + seg * 8;         \
            cp16(sbb_ + so,          Ahi + ga);                                \
            cp16(sbb_ + 10240 + so,  Alo + ga);                                \
            cp16(sbb_ + 20480 + so,  Bhi + gbx);                               \
            cp16(sbb_ + 30720 + so,  Blo + gbx);                               \
        }                                                                      \
        cp_commit();                                                           \
    } while (0)

    LOAD_CHUNK(0, 0);
    for (int ck = 0; ck < nck; ++ck) {
        if (ck + 1 < nck) { LOAD_CHUNK(ck + 1, (ck + 1) & 1); cp_wait<1>(); }
        else              { cp_wait<0>(); }
        __syncthreads();
        const uint32_t sbb = sb + (ck & 1) * 40960;
        #pragma unroll
        for (int step = 0; step < 2; ++step) {
            uint32_t av[4][4], bh[4][2], bl[4][2];
            #pragma unroll
            for (int mt = 0; mt < 4; ++mt)
                ldsm4(av[mt], sbb + (warpR * 64 + mt * 16) * 80 + step * 32 + aoff);
            #pragma unroll
            for (int nt = 0; nt < 4; ++nt) {
                ldsm2(bh[nt], sbb + 20480 + (warpC * 32 + nt * 8) * 80 + step * 32 + boff);
                ldsm2(bl[nt], sbb + 30720 + (warpC * 32 + nt * 8) * 80 + step * 32 + boff);
            }
            #pragma unroll
            for (int mt = 0; mt < 4; ++mt)
                #pragma unroll
                for (int nt = 0; nt < 4; ++nt)
                    mma16816(acc[mt][nt], av[mt], bh[nt]);
            #pragma unroll
            for (int mt = 0; mt < 4; ++mt)
                #pragma unroll
                for (int nt = 0; nt < 4; ++nt)
                    mma16816(acc[mt][nt], av[mt], bl[nt]);
            #pragma unroll
            for (int mt = 0; mt < 4; ++mt)
                ldsm4(av[mt], sbb + 10240 + (warpR * 64 + mt * 16) * 80 + step * 32 + aoff);
            #pragma unroll
            for (int mt = 0; mt < 4; ++mt)
                #pragma unroll
                for (int nt = 0; nt < 4; ++nt)
                    mma16816(acc[mt][nt], av[mt], bh[nt]);
        }
        __syncthreads();
    }
    #undef LOAD_CHUNK

    #define EPI acc, sm, m0, n0, warpR, warpC, lane, tid, a.Ah, a.Al, a.bias, a.e0, a.e1, a.alr
    if (MODE == M_PROJ3) {
        if (slot == 0) {
            passN<0>(EPI, a.ohi, a.olo);            // keys
            passT<0>(EPI, a.othi, a.otlo);          // keys^T
        } else if (slot == 1) {
            passN<0>(EPI, a.o2h, a.o2l);            // queries
        } else {
            passF<0>(EPI, a.f0);                    // values fp32
        }
    } else if (MODE == M_FWD_KT) {
        passF<1>(EPI, a.f0);                        // z1
        passN<2>(EPI, a.ohi, a.olo);                // h1
        passT<2>(EPI, a.othi, a.otlo);              // h1^T
    } else if (MODE == M_FWD_Q) {
        passN<2>(EPI, a.ohi, a.olo);
    } else if (MODE == M_FWD_OUT) {
        passF<2>(EPI, a.f0);
    } else if (MODE == M_DZ2) {
        passF<3>(EPI, a.f0);                        // dp
        passN<4>(EPI, a.ohi, a.olo);                // dz2
        passT<4>(EPI, a.othi, a.otlo);              // dz2^T
        biasPart(sm, m0, n0, tid, a.gbp);           // layer-1 bias partials
    } else if (MODE == M_DZ1) {
        passT<5>(EPI, a.othi, a.otlo);              // dz1^T
        biasPart(sm, m0, n0, tid, a.gbp);           // layer-0 bias partials
    } else {                                        // M_PART2: split-K partial
        passF<0>(EPI, a.f0 + (size_t)blockIdx.z * DD);
    }
    #undef EPI
}

// ---------------- x split + adaptive lr (fused, 8 tokens/block) -------------
__global__ void xsplit_alr(const float* __restrict__ x, const float* __restrict__ Wlr,
                           const float* __restrict__ blr,
                           __nv_bfloat16* __restrict__ xh, __nv_bfloat16* __restrict__ xl,
                           float* __restrict__ alr)
{
    const int warp = threadIdx.x >> 5, lane = threadIdx.x & 31;
    const long tok = (long)blockIdx.x * 8 + warp;
    const float* xr = x + tok * 256 + lane * 8;
    float4 va = *(const float4*)xr;
    float4 vb = *(const float4*)(xr + 4);
    float v[8] = {va.x, va.y, va.z, va.w, vb.x, vb.y, vb.z, vb.w};
    const float* wr = Wlr + lane * 8;
    float dot = 0.f;
    ushort hs[8], ls[8];
    #pragma unroll
    for (int j = 0; j < 8; ++j) {
        dot += v[j] * wr[j];
        __nv_bfloat16 h = __float2bfloat16(v[j]);
        hs[j] = __bfloat16_as_ushort(h);
        ls[j] = __bfloat16_as_ushort(__float2bfloat16(v[j] - __bfloat162float(h)));
    }
    *(uint4*)(xh + tok * 256 + lane * 8) = *(uint4*)hs;
    *(uint4*)(xl + tok * 256 + lane * 8) = *(uint4*)ls;
    #pragma unroll
    for (int o = 16; o > 0; o >>= 1) dot += __shfl_xor_sync(0xffffffffu, dot, o);
    if (lane == 0) alr[tok] = 0.1f * sigm(dot + blr[0]);
}

// ---------------- weight prep: [n][k] bf16 hi/lo -----------------------------
// slots: 0=Wk^T 1=Wq^T 2=Wv^T 3=W0^T 4=W1^T 5=W1
__global__ void wprep(const float* __restrict__ Wk, const float* __restrict__ Wq,
                      const float* __restrict__ Wv, const float* __restrict__ Ws,
                      __nv_bfloat16* __restrict__ wh, __nv_bfloat16* __restrict__ wl)
{
    const int idx = blockIdx.x * 256 + threadIdx.x;
    const int slot = idx >> 16;
    const int r = (idx >> 8) & 255;
    const int c = idx & 255;
    float v;
    if      (slot == 0) v = Wk[c * 256 + r];
    else if (slot == 1) v = Wq[c * 256 + r];
    else if (slot == 2) v = Wv[c * 256 + r];
    else if (slot == 3) v = Ws[c * 256 + r];
    else if (slot == 4) v = Ws[DD + c * 256 + r];
    else                v = Ws[DD + r * 256 + c];
    store_pair(wh, wl, idx, v);
}

// ---------------- split-K reduce for weight grads ---------------------------
// part slices 0..63 = h1^T@dz2 (gW1 / layer1); 64..127 = keys^T@dz1 (gW0 / layer0)
__global__ void gwred(const float* __restrict__ part, float* __restrict__ gW)
{
    const int i = blockIdx.x * 256 + threadIdx.x;   // 0..2*DD-1
    const int layer = i >> 16;
    const int j = i & 65535;
    const int zbase = (layer == 0) ? 64 : 0;
    float s = 0.0f;
    for (int z = 0; z < 64; ++z) s += part[(size_t)(zbase + z) * DD + j];
    gW[i] = s;
}

// ---------------- bias-grad reduce ------------------------------------------
__global__ void gbred(const float* __restrict__ gbp, float* __restrict__ gb)
{
    const int layer = blockIdx.x;       // 0 = dz1 (layer0), 1 = dz2 (layer1)
    const int j = threadIdx.x;
    const float* p = gbp + (size_t)layer * 65536;
    float s = 0.f;
    for (int mt = 0; mt < 256; ++mt) s += p[mt * 256 + j];
    gb[layer * 256 + j] = s;
}

// ---------------- AdamW step: out(-g), transposed bf16 updated weights ------
__global__ void adamw2(const float* __restrict__ Ws, const float* __restrict__ bs,
                       const float* __restrict__ gW, const float* __restrict__ gb,
                       __nv_bfloat16* __restrict__ nwth, __nv_bfloat16* __restrict__ nwtl,
                       float* __restrict__ nb, float* __restrict__ out)
{
    const int idx = blockIdx.x * 256 + threadIdx.x;
    const float decay = 1.0f - LRc * WDc;
    if (idx < 2 * DD) {
        const float g = gW[idx];
        out[ND + idx] = -g;
        const float nw = Ws[idx] * decay - LRc * g / (fabsf(g) + EPSc);
        const int layer = idx >> 16;
        const int k = (idx >> 8) & 255;
        const int n = idx & 255;
        store_pair(nwth, nwtl, (long)layer * DD + n * 256 + k, nw);
    } else if (idx < 2 * DD + 2 * D) {
        const int b = idx - 2 * DD;
        const float g = gb[b];
        out[ND + 2 * DD + b] = -g;
        nb[b] = bs[b] * decay - LRc * g / (fabsf(g) + EPSc);
    }
}

// ---------------------------------------------------------------------------
extern "C" void kernel_launch(void* const* d_in, const int* in_sizes, int n_in,
                              void* d_out, int out_size)
{
    const float* x   = (const float*)d_in[0];
    const float* Wk  = (const float*)d_in[1];
    const float* Wq  = (const float*)d_in[2];
    const float* Wv  = (const float*)d_in[3];
    const float* Wlr = (const float*)d_in[4];
    const float* blr = (const float*)d_in[5];
    const float* Ws  = (const float*)d_in[6];
    const float* bs  = (const float*)d_in[7];
    float* out = (float*)d_out;

    #define SYM(T, v, s) T* v; cudaGetSymbolAddress((void**)&v, s)
    SYM(__nv_bfloat16, xbh, g_xbh);   SYM(__nv_bfloat16, xbl, g_xbl);
    SYM(__nv_bfloat16, keysh, g_keysh); SYM(__nv_bfloat16, keysl, g_keysl);
    SYM(__nv_bfloat16, keysth, g_keysth); SYM(__nv_bfloat16, keystl, g_keystl);
    SYM(__nv_bfloat16, qh, g_qh);     SYM(__nv_bfloat16, ql, g_ql);
    SYM(__nv_bfloat16, h1h, g_h1h);   SYM(__nv_bfloat16, h1l, g_h1l);
    SYM(__nv_bfloat16, h1th, g_h1th); SYM(__nv_bfloat16, h1tl, g_h1tl);
    SYM(__nv_bfloat16, dz2h, g_dz2h); SYM(__nv_bfloat16, dz2l, g_dz2l);
    SYM(__nv_bfloat16, dz2th, g_dz2th); SYM(__nv_bfloat16, dz2tl, g_dz2tl);
    SYM(__nv_bfloat16, dz1th, g_dz1th); SYM(__nv_bfloat16, dz1tl, g_dz1tl);
    SYM(__nv_bfloat16, h1qh, g_h1qh); SYM(__nv_bfloat16, h1ql, g_h1ql);
    SYM(__nv_bfloat16, wbh, g_wbh);   SYM(__nv_bfloat16, wbl, g_wbl);
    SYM(__nv_bfloat16, nwth, g_nwth); SYM(__nv_bfloat16, nwtl, g_nwtl);
    SYM(float, values, g_values); SYM(float, z1, g_z1); SYM(float, dp, g_dp);
    SYM(float, part, g_part); SYM(float, gbp, g_gbp);
    SYM(float, gW, g_gW); SYM(float, gb, g_gb);
    SYM(float, nb, g_nb); SYM(float, alr, g_alr);
    #undef SYM

    #define SETSM(M) cudaFuncSetAttribute(mm_k<M>, \
        cudaFuncAttributeMaxDynamicSharedMemorySize, SMEM_BYTES)
    SETSM(M_PROJ3); SETSM(M_FWD_KT); SETSM(M_FWD_Q);
    SETSM(M_FWD_OUT); SETSM(M_DZ2); SETSM(M_DZ1); SETSM(M_PART2);
    #undef SETSM

    xsplit_alr<<<NTOK / 8, 256>>>(x, Wlr, blr, xbh, xbl, alr);
    wprep<<<6 * DD / 256, 256>>>(Wk, Wq, Wv, Ws, wbh, wbl);

    MMArgs a = {};
    a.lda = 256; a.ldb = 256; a.nck = 8;

    // fused projections: keys(+T), queries, values
    a.Ah = xbh; a.Al = xbl; a.Bh = wbh; a.Bl = wbl;
    a.ohi = keysh; a.olo = keysl; a.othi = keysth; a.otlo = keystl;
    a.o2h = qh; a.o2l = ql; a.f0 = values;
    mm_k<M_PROJ3><<<dim3(6, 256), 256, SMEM_BYTES>>>(a);

    // forward on keys: z1, h1, h1^T
    a = {}; a.lda = 256; a.ldb = 256; a.nck = 8;
    a.Ah = keysh; a.Al = keysl; a.Bh = wbh + 3 * DD; a.Bl = wbl + 3 * DD;
    a.bias = bs; a.f0 = z1;
    a.ohi = h1h; a.olo = h1l; a.othi = h1th; a.otlo = h1tl;
    mm_k<M_FWD_KT><<<dim3(2, 256), 256, SMEM_BYTES>>>(a);

    // dz2 (+dp) (+ layer-1 bias partials)
    a = {}; a.lda = 256; a.ldb = 256; a.nck = 8;
    a.Ah = h1h; a.Al = h1l; a.Bh = wbh + 4 * DD; a.Bl = wbl + 4 * DD;
    a.bias = bs + D; a.e0 = values; a.alr = alr; a.f0 = dp;
    a.ohi = dz2h; a.olo = dz2l; a.othi = dz2th; a.otlo = dz2tl;
    a.gbp = gbp + 65536;
    mm_k<M_DZ2><<<dim3(2, 256), 256, SMEM_BYTES>>>(a);

    // dz1 = (dp + dz2 @ W1^T) * silu'(z1)  (+ layer-0 bias partials)
    a = {}; a.lda = 256; a.ldb = 256; a.nck = 8;
    a.Ah = dz2h; a.Al = dz2l; a.Bh = wbh + 5 * DD; a.Bl = wbl + 5 * DD;
    a.e0 = dp; a.e1 = z1;
    a.othi = dz1th; a.otlo = dz1tl;
    a.gbp = gbp;
    mm_k<M_DZ1><<<dim3(2, 256), 256, SMEM_BYTES>>>(a);

    // merged weight-grad split-K: z<64 -> h1^T@dz2, z>=64 -> keys^T@dz1
    a = {}; a.lda = 32768; a.ldb = 32768; a.nck = 16;
    a.Ah = h1th; a.Al = h1tl; a.Bh = dz2th; a.Bl = dz2tl;
    a.A2h = keysth; a.A2l = keystl; a.B2h = dz1th; a.B2l = dz1tl;
    a.f0 = part;
    mm_k<M_PART2><<<dim3(2, 2, 128), 256, SMEM_BYTES>>>(a);
    gwred<<<2 * DD / 256, 256>>>(part, gW);
    gbred<<<2, 256>>>(gbp, gb);

    // AdamW update + emit -grads + transposed bf16 updated weights
    adamw2<<<(2 * DD + 2 * D + 255) / 256, 256>>>(Ws, bs, gW, gb, nwth, nwtl, nb, out);

    // retrieved = forward(queries) with updated weights
    a = {}; a.lda = 256; a.ldb = 256; a.nck = 8;
    a.Ah = qh; a.Al = ql; a.Bh = nwth; a.Bl = nwtl;
    a.bias = nb; a.ohi = h1qh; a.olo = h1ql;
    mm_k<M_FWD_Q><<<dim3(2, 256), 256, SMEM_BYTES>>>(a);

    a = {}; a.lda = 256; a.ldb = 256; a.nck = 8;
    a.Ah = h1qh; a.Al = h1ql; a.Bh = nwth + DD; a.Bl = nwtl + DD;
    a.bias = nb + D; a.f0 = out;
    mm_k<M_FWD_OUT><<<dim3(2, 256), 256, SMEM_BYTES>>>(a);
}

// round 5
// speedup vs baseline: 2.1361x; 1.2093x over previous
#include <cuda_runtime.h>
#include <cuda_bf16.h>
#include <math.h>
#include <stdint.h>

#define D      256
#define NTOK   32768
#define ND     (NTOK * D)
#define DD     (D * D)
#define LRc    1e-3f
#define WDc    1e-2f
#define EPSc   1e-8f

// ---------------- scratch (device globals: allocation-free) ----------------
__device__ __nv_bfloat16 g_xbh[ND],  g_xbl[ND];
__device__ __nv_bfloat16 g_keysh[ND], g_keysl[ND];
__device__ __nv_bfloat16 g_qh[ND],   g_ql[ND];
__device__ __nv_bfloat16 g_h1h[ND],  g_h1l[ND];
__device__ __nv_bfloat16 g_dz2h[ND], g_dz2l[ND];
__device__ __nv_bfloat16 g_dz1h[ND], g_dz1l[ND];
__device__ __nv_bfloat16 g_h1qh[ND], g_h1ql[ND];
__device__ __nv_bfloat16 g_wbh[6 * DD], g_wbl[6 * DD];
__device__ __nv_bfloat16 g_nwth[2 * DD], g_nwtl[2 * DD];
__device__ float g_values[ND], g_z1[ND], g_dp[ND];
__device__ float g_part[128 * DD];
__device__ float g_gbp[2 * 256 * 256];
__device__ float g_gW[2 * DD], g_gb[2 * D], g_nb[2 * D], g_alr[NTOK];

__device__ __forceinline__ float sigm(float z) { return 1.0f / (1.0f + expf(-z)); }

__device__ __forceinline__ uint32_t smem_u32(const void* p) {
    uint32_t a;
    asm("{ .reg .u64 t; cvta.to.shared.u64 t, %1; cvt.u32.u64 %0, t; }"
        : "=r"(a) : "l"(p));
    return a;
}

__device__ __forceinline__ void cp16(uint32_t dst, const void* src) {
    asm volatile("cp.async.cg.shared.global [%0], [%1], 16;"
                 :: "r"(dst), "l"(src) : "memory");
}
__device__ __forceinline__ void cp_commit() {
    asm volatile("cp.async.commit_group;" ::: "memory");
}
template <int N>
__device__ __forceinline__ void cp_wait() {
    asm volatile("cp.async.wait_group %0;" :: "n"(N) : "memory");
}

__device__ __forceinline__ void ldsm4(uint32_t* r, uint32_t a) {
    asm volatile("ldmatrix.sync.aligned.m8n8.x4.shared.b16 {%0,%1,%2,%3}, [%4];"
                 : "=r"(r[0]), "=r"(r[1]), "=r"(r[2]), "=r"(r[3]) : "r"(a));
}
__device__ __forceinline__ void ldsm2(uint32_t* r, uint32_t a) {
    asm volatile("ldmatrix.sync.aligned.m8n8.x2.shared.b16 {%0,%1}, [%2];"
                 : "=r"(r[0]), "=r"(r[1]) : "r"(a));
}
__device__ __forceinline__ void ldsm4t(uint32_t* r, uint32_t a) {
    asm volatile("ldmatrix.sync.aligned.m8n8.x4.trans.shared.b16 {%0,%1,%2,%3}, [%4];"
                 : "=r"(r[0]), "=r"(r[1]), "=r"(r[2]), "=r"(r[3]) : "r"(a));
}
__device__ __forceinline__ void ldsm2t(uint32_t* r, uint32_t a) {
    asm volatile("ldmatrix.sync.aligned.m8n8.x2.trans.shared.b16 {%0,%1}, [%2];"
                 : "=r"(r[0]), "=r"(r[1]) : "r"(a));
}

__device__ __forceinline__ void mma16816(float* c, const uint32_t* a, const uint32_t* b) {
    asm volatile(
        "mma.sync.aligned.m16n8k16.row.col.f32.bf16.bf16.f32 "
        "{%0,%1,%2,%3}, {%4,%5,%6,%7}, {%8,%9}, {%0,%1,%2,%3};"
        : "+f"(c[0]), "+f"(c[1]), "+f"(c[2]), "+f"(c[3])
        : "r"(a[0]), "r"(a[1]), "r"(a[2]), "r"(a[3]), "r"(b[0]), "r"(b[1]));
}

__device__ __forceinline__ void store_pair(__nv_bfloat16* oh, __nv_bfloat16* ol,
                                           long idx, float v) {
    __nv_bfloat16 h = __float2bfloat16(v);
    oh[idx] = h;
    ol[idx] = __float2bfloat16(v - __bfloat162float(h));
}

// ---------------- epilogue transforms ---------------------------------------
// TF: 0=raw 2=h(resid silu) 5=dz1
template <int TF>
__device__ __forceinline__ float2 xf(float v0, float v1, int R, int C,
    const __nv_bfloat16* __restrict__ Ahi, const __nv_bfloat16* __restrict__ Alo,
    const float* __restrict__ bias, const float* __restrict__ e0,
    const float* __restrict__ e1)
{
    if (TF == 0) return make_float2(v0, v1);
    if (TF == 5) {
        float2 ed = *reinterpret_cast<const float2*>(e0 + (size_t)R * 256 + C);
        float2 ez = *reinterpret_cast<const float2*>(e1 + (size_t)R * 256 + C);
        float dh0 = ed.x + v0, dh1 = ed.y + v1;
        float s0 = sigm(ez.x), s1 = sigm(ez.y);
        return make_float2(dh0 * s0 * (1.f + ez.x * (1.f - s0)),
                           dh1 * s1 * (1.f + ez.y * (1.f - s1)));
    }
    // TF == 2
    float z0 = v0 + bias[C], z1v = v1 + bias[C + 1];
    float s0 = sigm(z0), s1 = sigm(z1v);
    __nv_bfloat162 ah = *reinterpret_cast<const __nv_bfloat162*>(Ahi + (size_t)R * 256 + C);
    __nv_bfloat162 al = *reinterpret_cast<const __nv_bfloat162*>(Alo + (size_t)R * 256 + C);
    float a0 = __bfloat162float(ah.x) + __bfloat162float(al.x);
    float a1 = __bfloat162float(ah.y) + __bfloat162float(al.y);
    return make_float2(a0 + z0 * s0, a1 + z1v * s1);
}

#define EPI_ARGS float (&acc)[4][4][4], char* sm, int m0, int n0, int warpR, int warpC, \
    int lane, int tid, const __nv_bfloat16* __restrict__ Ahi, \
    const __nv_bfloat16* __restrict__ Alo, const float* __restrict__ bias, \
    const float* __restrict__ e0, const float* __restrict__ e1

// normal-layout bf16 hi/lo store, smem-staged, coalesced
template <int TF>
__device__ __forceinline__ void passN(EPI_ARGS,
    __nv_bfloat16* __restrict__ ohi, __nv_bfloat16* __restrict__ olo)
{
    __syncthreads();
    uint32_t* s0 = (uint32_t*)sm;
    uint32_t* s1 = (uint32_t*)(sm + 34816);
    #pragma unroll
    for (int mt = 0; mt < 4; ++mt)
        #pragma unroll
        for (int h = 0; h < 2; ++h) {
            const int rl = warpR * 64 + mt * 16 + (lane >> 2) + h * 8;
            const int R = m0 + rl;
            #pragma unroll
            for (int nt = 0; nt < 4; ++nt) {
                const int cl = warpC * 32 + nt * 8 + 2 * (lane & 3);
                float2 t = xf<TF>(acc[mt][nt][2 * h], acc[mt][nt][2 * h + 1],
                                  R, n0 + cl, Ahi, Alo, bias, e0, e1);
                __nv_bfloat16 bh0 = __float2bfloat16(t.x), bh1 = __float2bfloat16(t.y);
                __nv_bfloat16 bl0 = __float2bfloat16(t.x - __bfloat162float(bh0));
                __nv_bfloat16 bl1 = __float2bfloat16(t.y - __bfloat162float(bh1));
                const int w = rl * 68 + (cl >> 1);
                s0[w] = (uint32_t)__bfloat16_as_ushort(bh0)
                      | ((uint32_t)__bfloat16_as_ushort(bh1) << 16);
                s1[w] = (uint32_t)__bfloat16_as_ushort(bl0)
                      | ((uint32_t)__bfloat16_as_ushort(bl1) << 16);
            }
        }
    __syncthreads();
    #pragma unroll
    for (int it = 0; it < 8; ++it) {
        const int row = it * 16 + (tid >> 4), seg = tid & 15;
        uint4 vh = *(uint4*)(sm + row * 272 + seg * 16);
        uint4 vl = *(uint4*)(sm + 34816 + row * 272 + seg * 16);
        *(uint4*)(ohi + (size_t)(m0 + row) * 256 + n0 + seg * 8) = vh;
        *(uint4*)(olo + (size_t)(m0 + row) * 256 + n0 + seg * 8) = vl;
    }
}

// bias-grad partials from N staging (hi+lo): column sums over 128 tokens.
__device__ __forceinline__ void biasN(char* sm, int m0, int n0, int tid,
                                      float* __restrict__ gbp)
{
    const int c = tid & 63, q = tid >> 6;          // colpair, row quarter
    const uint32_t* s0 = (const uint32_t*)sm;
    const uint32_t* s1 = (const uint32_t*)(sm + 34816);
    float se = 0.f, so = 0.f;
    #pragma unroll 8
    for (int r = q * 32; r < q * 32 + 32; ++r) {
        uint32_t w0 = s0[r * 68 + c], w1 = s1[r * 68 + c];
        __nv_bfloat162 a = *(const __nv_bfloat162*)&w0;
        __nv_bfloat162 b = *(const __nv_bfloat162*)&w1;
        se += __bfloat162float(a.x) + __bfloat162float(b.x);
        so += __bfloat162float(a.y) + __bfloat162float(b.y);
    }
    float* tmp = (float*)(sm + 70656);
    tmp[q * 128 + c * 2]     = se;
    tmp[q * 128 + c * 2 + 1] = so;
    __syncthreads();
    if (tid < 128)
        gbp[(m0 >> 7) * 256 + n0 + tid] =
            tmp[tid] + tmp[128 + tid] + tmp[256 + tid] + tmp[384 + tid];
}

// store half of fp32 pass (reads 528B-stride staging)
__device__ __forceinline__ void storeF(char* sm, int m0, int n0, int tid,
                                       float* __restrict__ f0)
{
    #pragma unroll
    for (int it = 0; it < 16; ++it) {
        const int row = it * 8 + (tid >> 5), seg = tid & 31;
        uint4 v = *(uint4*)(sm + row * 528 + seg * 16);
        *(uint4*)(f0 + (size_t)(m0 + row) * 256 + n0 + seg * 4) = v;
    }
}

// fp32 store, smem-staged, with transform
template <int TF>
__device__ __forceinline__ void passF(EPI_ARGS, float* __restrict__ f0)
{
    __syncthreads();
    #pragma unroll
    for (int mt = 0; mt < 4; ++mt)
        #pragma unroll
        for (int h = 0; h < 2; ++h) {
            const int rl = warpR * 64 + mt * 16 + (lane >> 2) + h * 8;
            const int R = m0 + rl;
            #pragma unroll
            for (int nt = 0; nt < 4; ++nt) {
                const int cl = warpC * 32 + nt * 8 + 2 * (lane & 3);
                float2 t = xf<TF>(acc[mt][nt][2 * h], acc[mt][nt][2 * h + 1],
                                  R, n0 + cl, Ahi, Alo, bias, e0, e1);
                *(float2*)(sm + rl * 528 + cl * 4) = t;
            }
        }
    __syncthreads();
    storeF(sm, m0, n0, tid, f0);
}

// combined transform: stage fp32 (z1 or dp) to smem, leave bf16-source in acc.
// IS_DZ2=0: stage z, acc=h (residual silu). IS_DZ2=1: stage d, acc=dz2.
template <int IS_DZ2>
__device__ __forceinline__ void combinedTF(float (&acc)[4][4][4], char* sm,
    int m0, int n0, int warpR, int warpC, int lane,
    const __nv_bfloat16* __restrict__ Ahi, const __nv_bfloat16* __restrict__ Alo,
    const float* __restrict__ bias, const float* __restrict__ e0,
    const float* __restrict__ alr_)
{
    __syncthreads();
    #pragma unroll
    for (int mt = 0; mt < 4; ++mt)
        #pragma unroll
        for (int h = 0; h < 2; ++h) {
            const int rl = warpR * 64 + mt * 16 + (lane >> 2) + h * 8;
            const int R = m0 + rl;
            float cf = 0.f;
            if (IS_DZ2) cf = alr_[R] * 0.0078125f;
            #pragma unroll
            for (int nt = 0; nt < 4; ++nt) {
                const int cl = warpC * 32 + nt * 8 + 2 * (lane & 3);
                const int C = n0 + cl;
                const size_t idx = (size_t)R * 256 + C;
                float z0 = acc[mt][nt][2 * h]     + bias[C];
                float z1v = acc[mt][nt][2 * h + 1] + bias[C + 1];
                float s0 = sigm(z0), s1 = sigm(z1v);
                __nv_bfloat162 ah = *(const __nv_bfloat162*)(Ahi + idx);
                __nv_bfloat162 al = *(const __nv_bfloat162*)(Alo + idx);
                float a0 = __bfloat162float(ah.x) + __bfloat162float(al.x);
                float a1 = __bfloat162float(ah.y) + __bfloat162float(al.y);
                float h0 = a0 + z0 * s0, h1v = a1 + z1v * s1;
                if (!IS_DZ2) {
                    *(float2*)(sm + rl * 528 + cl * 4) = make_float2(z0, z1v);
                    acc[mt][nt][2 * h] = h0;
                    acc[mt][nt][2 * h + 1] = h1v;
                } else {
                    float2 e = *(const float2*)(e0 + idx);
                    float d0 = cf * (h0 - e.x), d1 = cf * (h1v - e.y);
                    *(float2*)(sm + rl * 528 + cl * 4) = make_float2(d0, d1);
                    acc[mt][nt][2 * h]     = d0 * s0 * (1.f + z0 * (1.f - s0));
                    acc[mt][nt][2 * h + 1] = d1 * s1 * (1.f + z1v * (1.f - s1));
                }
            }
        }
    __syncthreads();
}

// ---------------- mma.sync GEMM: C[128 x 128] tile, 3-term bf16 split -------
enum { M_PROJ3 = 0, M_FWD_KT, M_FWD_Q, M_FWD_OUT, M_DZ2, M_DZ1 };

#define SMEM_BYTES 81920

struct MMArgs {
    const __nv_bfloat16 *Ah, *Al, *Bh, *Bl;
    const float *bias, *e0, *e1, *alr;
    float *f0, *gbp;
    __nv_bfloat16 *ohi, *olo, *o2h, *o2l;
};

template <int MODE>
__global__ __launch_bounds__(256, 2) void mm_k(const MMArgs a)
{
    extern __shared__ char sm[];
    const int tid = threadIdx.x, lane = tid & 31, wid = tid >> 5;
    const int warpR = wid >> 2, warpC = wid & 3;
    const int m0 = blockIdx.y * 128;
    const int n0 = (MODE == M_PROJ3 ? (blockIdx.x & 1) * 128 : blockIdx.x * 128);
    const uint32_t sb = smem_u32(sm);

    const __nv_bfloat16 *Ahi = a.Ah, *Alo = a.Al, *Bhi = a.Bh, *Blo = a.Bl;
    int slot = 0;
    if (MODE == M_PROJ3) {
        slot = blockIdx.x >> 1;
        Bhi = a.Bh + (size_t)slot * DD;
        Blo = a.Bl + (size_t)slot * DD;
    }

    float acc[4][4][4];
    #pragma unroll
    for (int i = 0; i < 4; ++i)
        #pragma unroll
        for (int j = 0; j < 4; ++j)
            #pragma unroll
            for (int e = 0; e < 4; ++e) acc[i][j][e] = 0.f;

    const uint32_t aoff = (uint32_t)((((lane & 7) + ((lane >> 3) & 1) * 8)) * 80
                                     + (lane >> 4) * 16);
    const int lb = lane & 15;
    const uint32_t boff = (uint32_t)((lb & 7) * 80 + (lb >> 3) * 16);

    #define LOAD_CHUNK(ck, buf) do {                                           \
        const int k0_ = (ck) * 32;                                             \
        const uint32_t sbb_ = sb + (buf) * 40960;                              \
        _Pragma("unroll")                                                      \
        for (int rep = 0; rep < 2; ++rep) {                                    \
            const int id = tid + rep * 256;                                    \
            const int row = id >> 2, seg = id & 3;                             \
            const uint32_t so = row * 80 + seg * 16;                           \
            const long ga = (long)(m0 + row) * 256 + k0_ + seg * 8;            \
            const long gbx = (long)(n0 + row) * 256 + k0_ + seg * 8;           \
            cp16(sbb_ + so,          Ahi + ga);                                \
            cp16(sbb_ + 10240 + so,  Alo + ga);                                \
            cp16(sbb_ + 20480 + so,  Bhi + gbx);                               \
            cp16(sbb_ + 30720 + so,  Blo + gbx);                               \
        }                                                                      \
        cp_commit();                                                           \
    } while (0)

    LOAD_CHUNK(0, 0);
    #pragma unroll 1
    for (int ck = 0; ck < 8; ++ck) {
        cp_wait<0>();
        __syncthreads();
        if (ck + 1 < 8) LOAD_CHUNK(ck + 1, (ck + 1) & 1);
        const uint32_t sbb = sb + (ck & 1) * 40960;
        #pragma unroll
        for (int step = 0; step < 2; ++step) {
            uint32_t av[4][4], bh[4][2], bl[4][2];
            #pragma unroll
            for (int mt = 0; mt < 4; ++mt)
                ldsm4(av[mt], sbb + (warpR * 64 + mt * 16) * 80 + step * 32 + aoff);
            #pragma unroll
            for (int nt = 0; nt < 4; ++nt) {
                ldsm2(bh[nt], sbb + 20480 + (warpC * 32 + nt * 8) * 80 + step * 32 + boff);
                ldsm2(bl[nt], sbb + 30720 + (warpC * 32 + nt * 8) * 80 + step * 32 + boff);
            }
            #pragma unroll
            for (int mt = 0; mt < 4; ++mt)
                #pragma unroll
                for (int nt = 0; nt < 4; ++nt)
                    mma16816(acc[mt][nt], av[mt], bh[nt]);
            #pragma unroll
            for (int mt = 0; mt < 4; ++mt)
                #pragma unroll
                for (int nt = 0; nt < 4; ++nt)
                    mma16816(acc[mt][nt], av[mt], bl[nt]);
            #pragma unroll
            for (int mt = 0; mt < 4; ++mt)
                ldsm4(av[mt], sbb + 10240 + (warpR * 64 + mt * 16) * 80 + step * 32 + aoff);
            #pragma unroll
            for (int mt = 0; mt < 4; ++mt)
                #pragma unroll
                for (int nt = 0; nt < 4; ++nt)
                    mma16816(acc[mt][nt], av[mt], bh[nt]);
        }
    }
    #undef LOAD_CHUNK

    #define EPI acc, sm, m0, n0, warpR, warpC, lane, tid, a.Ah, a.Al, a.bias, a.e0, a.e1
    if (MODE == M_PROJ3) {
        if (slot == 2)      passF<0>(EPI, a.f0);              // values fp32
        else if (slot == 1) passN<0>(EPI, a.o2h, a.o2l);      // queries
        else                passN<0>(EPI, a.ohi, a.olo);      // keys
    } else if (MODE == M_FWD_KT) {
        combinedTF<0>(acc, sm, m0, n0, warpR, warpC, lane, a.Ah, a.Al, a.bias,
                      nullptr, nullptr);
        storeF(sm, m0, n0, tid, a.f0);                        // z1
        passN<0>(EPI, a.ohi, a.olo);                          // h1
    } else if (MODE == M_FWD_Q) {
        passN<2>(EPI, a.ohi, a.olo);
    } else if (MODE == M_FWD_OUT) {
        passF<2>(EPI, a.f0);
    } else if (MODE == M_DZ2) {
        combinedTF<1>(acc, sm, m0, n0, warpR, warpC, lane, a.Ah, a.Al, a.bias,
                      a.e0, a.alr);
        storeF(sm, m0, n0, tid, a.f0);                        // dp
        passN<0>(EPI, a.ohi, a.olo);                          // dz2
        biasN(sm, m0, n0, tid, a.gbp);                        // layer-1 bias partials
    } else {                                                  // M_DZ1
        passN<5>(EPI, a.ohi, a.olo);                          // dz1
        biasN(sm, m0, n0, tid, a.gbp);                        // layer-0 bias partials
    }
    #undef EPI
}

// ---------------- weight-grad GEMM via ldmatrix.trans on normal layout ------
// C[k1(128), k2(128)] += sum_n A[n][k1] * B[n][k2], tokens n chunked by 32.
// grid (2, 2, 128): x=n-tile, y=m-tile, z: [0,64)=h1ᵀ@dz2, [64,128)=keysᵀ@dz1
struct WGArgs {
    const __nv_bfloat16 *A1h, *A1l, *B1h, *B1l;
    const __nv_bfloat16 *A2h, *A2l, *B2h, *B2l;
    float* part;
};

__global__ __launch_bounds__(256, 2) void wg_k(const WGArgs a)
{
    extern __shared__ char sm[];
    const int tid = threadIdx.x, lane = tid & 31, wid = tid >> 5;
    const int warpR = wid >> 2, warpC = wid & 3;
    const int m0 = blockIdx.y * 128, n0 = blockIdx.x * 128;
    const int gemm = blockIdx.z >> 6;
    const long tokbase = (long)(blockIdx.z & 63) * 512;
    const uint32_t sb = smem_u32(sm);

    const __nv_bfloat16* Ah = gemm ? a.A2h : a.A1h;
    const __nv_bfloat16* Al = gemm ? a.A2l : a.A1l;
    const __nv_bfloat16* Bh = gemm ? a.B2h : a.B1h;
    const __nv_bfloat16* Bl = gemm ? a.B2l : a.B1l;

    float acc[4][4][4];
    #pragma unroll
    for (int i = 0; i < 4; ++i)
        #pragma unroll
        for (int j = 0; j < 4; ++j)
            #pragma unroll
            for (int e = 0; e < 4; ++e) acc[i][j][e] = 0.f;

    // trans fragment lane offsets (272B token-row stride)
    const uint32_t atoff = (uint32_t)((((lane >> 4) & 1) * 8 + (lane & 7)) * 272
                                      + ((lane >> 3) & 1) * 16);
    const int lb = lane & 15;
    const uint32_t btoff = (uint32_t)((((lb >> 3) & 1) * 8 + (lb & 7)) * 272);

    #define WLOAD(ck, buf) do {                                                \
        const long t0 = tokbase + (long)(ck) * 32;                             \
        const uint32_t sbb_ = sb + (buf) * 34816;                              \
        _Pragma("unroll")                                                      \
        for (int rep = 0; rep < 2; ++rep) {                                    \
            const int id = tid + rep * 256;                                    \
            const int row = id >> 4, seg = id & 15;                            \
            const uint32_t so = row * 272 + seg * 16;                          \
            const long gA = (t0 + row) * 256 + m0 + seg * 8;                   \
            const long gB = (t0 + row) * 256 + n0 + seg * 8;                   \
            cp16(sbb_ + so,          Ah + gA);                                 \
            cp16(sbb_ + 8704 + so,   Al + gA);                                 \
            cp16(sbb_ + 17408 + so,  Bh + gB);                                 \
            cp16(sbb_ + 26112 + so,  Bl + gB);                                 \
        }                                                                      \
        cp_commit();                                                           \
    } while (0)

    WLOAD(0, 0);
    #pragma unroll 1
    for (int ck = 0; ck < 16; ++ck) {
        cp_wait<0>();
        __syncthreads();
        if (ck + 1 < 16) WLOAD(ck + 1, (ck + 1) & 1);
        const uint32_t sbb = sb + (ck & 1) * 34816;
        #pragma unroll
        for (int step = 0; step < 2; ++step) {
            const uint32_t ks = step * 16 * 272;
            uint32_t av[4][4], bh[4][2], bl[4][2];
            #pragma unroll
            for (int mt = 0; mt < 4; ++mt)
                ldsm4t(av[mt], sbb + ks + atoff + (warpR * 64 + mt * 16) * 2);
            #pragma unroll
            for (int nt = 0; nt < 4; ++nt) {
                const uint32_t nb = (warpC * 32 + nt * 8) * 2;
                ldsm2t(bh[nt], sbb + 17408 + ks + btoff + nb);
                ldsm2t(bl[nt], sbb + 26112 + ks + btoff + nb);
            }
            #pragma unroll
            for (int mt = 0; mt < 4; ++mt)
                #pragma unroll
                for (int nt = 0; nt < 4; ++nt)
                    mma16816(acc[mt][nt], av[mt], bh[nt]);
            #pragma unroll
            for (int mt = 0; mt < 4; ++mt)
                #pragma unroll
                for (int nt = 0; nt < 4; ++nt)
                    mma16816(acc[mt][nt], av[mt], bl[nt]);
            #pragma unroll
            for (int mt = 0; mt < 4; ++mt)
                ldsm4t(av[mt], sbb + 8704 + ks + atoff + (warpR * 64 + mt * 16) * 2);
            #pragma unroll
            for (int mt = 0; mt < 4; ++mt)
                #pragma unroll
                for (int nt = 0; nt < 4; ++nt)
                    mma16816(acc[mt][nt], av[mt], bh[nt]);
        }
    }
    #undef WLOAD

    passF<0>(acc, sm, m0, n0, warpR, warpC, lane, tid, nullptr, nullptr,
             nullptr, nullptr, nullptr, a.part + (size_t)blockIdx.z * DD);
}

// ---------------- x split + adaptive lr (fused, 8 tokens/block) -------------
__global__ void xsplit_alr(const float* __restrict__ x, const float* __restrict__ Wlr,
                           const float* __restrict__ blr,
                           __nv_bfloat16* __restrict__ xh, __nv_bfloat16* __restrict__ xl,
                           float* __restrict__ alr)
{
    const int warp = threadIdx.x >> 5, lane = threadIdx.x & 31;
    const long tok = (long)blockIdx.x * 8 + warp;
    const float* xr = x + tok * 256 + lane * 8;
    float4 va = *(const float4*)xr;
    float4 vb = *(const float4*)(xr + 4);
    float v[8] = {va.x, va.y, va.z, va.w, vb.x, vb.y, vb.z, vb.w};
    const float* wr = Wlr + lane * 8;
    float dot = 0.f;
    ushort hs[8], ls[8];
    #pragma unroll
    for (int j = 0; j < 8; ++j) {
        dot += v[j] * wr[j];
        __nv_bfloat16 h = __float2bfloat16(v[j]);
        hs[j] = __bfloat16_as_ushort(h);
        ls[j] = __bfloat16_as_ushort(__float2bfloat16(v[j] - __bfloat162float(h)));
    }
    *(uint4*)(xh + tok * 256 + lane * 8) = *(uint4*)hs;
    *(uint4*)(xl + tok * 256 + lane * 8) = *(uint4*)ls;
    #pragma unroll
    for (int o = 16; o > 0; o >>= 1) dot += __shfl_xor_sync(0xffffffffu, dot, o);
    if (lane == 0) alr[tok] = 0.1f * sigm(dot + blr[0]);
}

// ---------------- weight prep: [n][k] bf16 hi/lo -----------------------------
// slots: 0=Wk^T 1=Wq^T 2=Wv^T 3=W0^T 4=W1^T 5=W1
__global__ void wprep(const float* __restrict__ Wk, const float* __restrict__ Wq,
                      const float* __restrict__ Wv, const float* __restrict__ Ws,
                      __nv_bfloat16* __restrict__ wh, __nv_bfloat16* __restrict__ wl)
{
    const int idx = blockIdx.x * 256 + threadIdx.x;
    const int slot = idx >> 16;
    const int r = (idx >> 8) & 255;
    const int c = idx & 255;
    float v;
    if      (slot == 0) v = Wk[c * 256 + r];
    else if (slot == 1) v = Wq[c * 256 + r];
    else if (slot == 2) v = Wv[c * 256 + r];
    else if (slot == 3) v = Ws[c * 256 + r];
    else if (slot == 4) v = Ws[DD + c * 256 + r];
    else                v = Ws[DD + r * 256 + c];
    store_pair(wh, wl, idx, v);
}

// ---------------- split-K reduce for weight grads ---------------------------
// part slices 0..63 = h1^T@dz2 (gW1/layer1); 64..127 = keys^T@dz1 (gW0/layer0)
__global__ void gwred(const float* __restrict__ part, float* __restrict__ gW)
{
    const int i = blockIdx.x * 256 + threadIdx.x;   // 0..2*DD-1
    const int layer = i >> 16;
    const int j = i & 65535;
    const int zbase = (layer == 0) ? 64 : 0;
    float s = 0.0f;
    for (int z = 0; z < 64; ++z) s += part[(size_t)(zbase + z) * DD + j];
    gW[i] = s;
}

// ---------------- bias-grad reduce ------------------------------------------
__global__ void gbred(const float* __restrict__ gbp, float* __restrict__ gb)
{
    const int layer = blockIdx.x;       // 0 = dz1 (layer0), 1 = dz2 (layer1)
    const int j = threadIdx.x;
    const float* p = gbp + (size_t)layer * 65536;
    float s = 0.f;
    for (int mt = 0; mt < 256; ++mt) s += p[mt * 256 + j];
    gb[layer * 256 + j] = s;
}

// ---------------- AdamW step: out(-g), transposed bf16 updated weights ------
__global__ void adamw2(const float* __restrict__ Ws, const float* __restrict__ bs,
                       const float* __restrict__ gW, const float* __restrict__ gb,
                       __nv_bfloat16* __restrict__ nwth, __nv_bfloat16* __restrict__ nwtl,
                       float* __restrict__ nb, float* __restrict__ out)
{
    const int idx = blockIdx.x * 256 + threadIdx.x;
    const float decay = 1.0f - LRc * WDc;
    if (idx < 2 * DD) {
        const float g = gW[idx];
        out[ND + idx] = -g;
        const float nw = Ws[idx] * decay - LRc * g / (fabsf(g) + EPSc);
        const int layer = idx >> 16;
        const int k = (idx >> 8) & 255;
        const int n = idx & 255;
        store_pair(nwth, nwtl, (long)layer * DD + n * 256 + k, nw);
    } else if (idx < 2 * DD + 2 * D) {
        const int b = idx - 2 * DD;
        const float g = gb[b];
        out[ND + 2 * DD + b] = -g;
        nb[b] = bs[b] * decay - LRc * g / (fabsf(g) + EPSc);
    }
}

// ---------------------------------------------------------------------------
extern "C" void kernel_launch(void* const* d_in, const int* in_sizes, int n_in,
                              void* d_out, int out_size)
{
    const float* x   = (const float*)d_in[0];
    const float* Wk  = (const float*)d_in[1];
    const float* Wq  = (const float*)d_in[2];
    const float* Wv  = (const float*)d_in[3];
    const float* Wlr = (const float*)d_in[4];
    const float* blr = (const float*)d_in[5];
    const float* Ws  = (const float*)d_in[6];
    const float* bs  = (const float*)d_in[7];
    float* out = (float*)d_out;

    #define SYM(T, v, s) T* v; cudaGetSymbolAddress((void**)&v, s)
    SYM(__nv_bfloat16, xbh, g_xbh);   SYM(__nv_bfloat16, xbl, g_xbl);
    SYM(__nv_bfloat16, keysh, g_keysh); SYM(__nv_bfloat16, keysl, g_keysl);
    SYM(__nv_bfloat16, qh, g_qh);     SYM(__nv_bfloat16, ql, g_ql);
    SYM(__nv_bfloat16, h1h, g_h1h);   SYM(__nv_bfloat16, h1l, g_h1l);
    SYM(__nv_bfloat16, dz2h, g_dz2h); SYM(__nv_bfloat16, dz2l, g_dz2l);
    SYM(__nv_bfloat16, dz1h, g_dz1h); SYM(__nv_bfloat16, dz1l, g_dz1l);
    SYM(__nv_bfloat16, h1qh, g_h1qh); SYM(__nv_bfloat16, h1ql, g_h1ql);
    SYM(__nv_bfloat16, wbh, g_wbh);   SYM(__nv_bfloat16, wbl, g_wbl);
    SYM(__nv_bfloat16, nwth, g_nwth); SYM(__nv_bfloat16, nwtl, g_nwtl);
    SYM(float, values, g_values); SYM(float, z1, g_z1); SYM(float, dp, g_dp);
    SYM(float, part, g_part); SYM(float, gbp, g_gbp);
    SYM(float, gW, g_gW); SYM(float, gb, g_gb);
    SYM(float, nb, g_nb); SYM(float, alr, g_alr);
    #undef SYM

    #define SETSM(M) cudaFuncSetAttribute(mm_k<M>, \
        cudaFuncAttributeMaxDynamicSharedMemorySize, SMEM_BYTES)
    SETSM(M_PROJ3); SETSM(M_FWD_KT); SETSM(M_FWD_Q);
    SETSM(M_FWD_OUT); SETSM(M_DZ2); SETSM(M_DZ1);
    #undef SETSM
    cudaFuncSetAttribute(wg_k, cudaFuncAttributeMaxDynamicSharedMemorySize, SMEM_BYTES);

    xsplit_alr<<<NTOK / 8, 256>>>(x, Wlr, blr, xbh, xbl, alr);
    wprep<<<6 * DD / 256, 256>>>(Wk, Wq, Wv, Ws, wbh, wbl);

    MMArgs a = {};
    // fused projections: keys, queries, values
    a.Ah = xbh; a.Al = xbl; a.Bh = wbh; a.Bl = wbl;
    a.ohi = keysh; a.olo = keysl; a.o2h = qh; a.o2l = ql; a.f0 = values;
    mm_k<M_PROJ3><<<dim3(6, 256), 256, SMEM_BYTES>>>(a);

    // forward on keys: z1 (fp32) + h1 (bf16 pair)
    a = {};
    a.Ah = keysh; a.Al = keysl; a.Bh = wbh + 3 * DD; a.Bl = wbl + 3 * DD;
    a.bias = bs; a.f0 = z1; a.ohi = h1h; a.olo = h1l;
    mm_k<M_FWD_KT><<<dim3(2, 256), 256, SMEM_BYTES>>>(a);

    // dz2 + dp + layer-1 bias partials (z2 recomputed in epilogue)
    a = {};
    a.Ah = h1h; a.Al = h1l; a.Bh = wbh + 4 * DD; a.Bl = wbl + 4 * DD;
    a.bias = bs + D; a.e0 = values; a.alr = alr; a.f0 = dp;
    a.ohi = dz2h; a.olo = dz2l; a.gbp = gbp + 65536;
    mm_k<M_DZ2><<<dim3(2, 256), 256, SMEM_BYTES>>>(a);

    // dz1 = (dp + dz2 @ W1^T) * silu'(z1)  + layer-0 bias partials
    a = {};
    a.Ah = dz2h; a.Al = dz2l; a.Bh = wbh + 5 * DD; a.Bl = wbl + 5 * DD;
    a.e0 = dp; a.e1 = z1; a.ohi = dz1h; a.olo = dz1l; a.gbp = gbp;
    mm_k<M_DZ1><<<dim3(2, 256), 256, SMEM_BYTES>>>(a);

    // weight grads from NORMAL layouts via ldmatrix.trans (split-K 64 each)
    WGArgs w = {};
    w.A1h = h1h;   w.A1l = h1l;   w.B1h = dz2h; w.B1l = dz2l;
    w.A2h = keysh; w.A2l = keysl; w.B2h = dz1h; w.B2l = dz1l;
    w.part = part;
    wg_k<<<dim3(2, 2, 128), 256, SMEM_BYTES>>>(w);
    gwred<<<2 * DD / 256, 256>>>(part, gW);
    gbred<<<2, 256>>>(gbp, gb);

    // AdamW update + emit -grads + transposed bf16 updated weights
    adamw2<<<(2 * DD + 2 * D + 255) / 256, 256>>>(Ws, bs, gW, gb, nwth, nwtl, nb, out);

    // retrieved = forward(queries) with updated weights
    a = {};
    a.Ah = qh; a.Al = ql; a.Bh = nwth; a.Bl = nwtl;
    a.bias = nb; a.ohi = h1qh; a.olo = h1ql;
    mm_k<M_FWD_Q><<<dim3(2, 256), 256, SMEM_BYTES>>>(a);

    a = {};
    a.Ah = h1qh; a.Al = h1ql; a.Bh = nwth + DD; a.Bl = nwtl + DD;
    a.bias = nb + D; a.f0 = out;
    mm_k<M_FWD_OUT><<<dim3(2, 256), 256, SMEM_BYTES>>>(a);
}